// round 15
// baseline (speedup 1.0000x reference)
#include <cuda_runtime.h>
#include <cuda.h>
#include <cstdint>
#include <math.h>

#define BB 256
#define CC 256
#define NN 196
#define MM (BB*NN)        // 50176
#define CMID 2048
#define EPSL 1e-5f

#if defined(__CUDA_ARCH_FEAT_SM103_ALL) || defined(__CUDA_ARCH_FEAT_SM100_ALL) || defined(__CUDA_ARCH_FEAT_SM101_ALL)
#define TC_OK 1
#else
#define TC_OK 0
#endif

// ---------------- scratch (device globals) -----------------------------------
__device__ float g_t   [(size_t)MM*CC];
__device__ float g_qkv [(size_t)MM*3*CC];
__device__ float g_attn[(size_t)MM*CC];
__device__ float g_t1  [(size_t)MM*CC];
__device__ float g_h   [(size_t)MM*CMID];
__device__ float g_wqkvT[(size_t)3*CC*CC];   // [768,256]
__device__ float g_wprojT[(size_t)CC*CC];    // [256,256]
__device__ float g_w1T  [(size_t)CMID*CC];   // [2048,256]
__device__ float g_w2T  [(size_t)CC*CMID];   // [256,2048]

// ---------------- PTX helpers -------------------------------------------------
__device__ __forceinline__ uint32_t smem_u32(const void* p) {
    uint32_t a;
    asm("{ .reg .u64 t; cvta.to.shared.u64 t, %1; cvt.u32.u64 %0, t; }" : "=r"(a) : "l"(p));
    return a;
}

#define MBAR_INIT(addr, cnt) \
    asm volatile("mbarrier.init.shared.b64 [%0], %1;" :: "r"(addr), "r"(cnt) : "memory")

#define MBAR_WAIT(addr, parity) do {                                              \
    uint32_t _m = (addr); uint32_t _p = (parity); uint32_t _d;                    \
    asm volatile("{\n\t.reg .pred p;\n\t"                                         \
        "mbarrier.try_wait.parity.acquire.cta.shared::cta.b64 p, [%1], %2;\n\t"   \
        "selp.b32 %0, 1, 0, p;\n\t}" : "=r"(_d) : "r"(_m), "r"(_p) : "memory");   \
    if (!_d) {                                                                     \
        asm volatile("{\n\t.reg .pred P1;\n\t"                                     \
            "W_%=:\n\t"                                                            \
            "mbarrier.try_wait.parity.acquire.cta.shared::cta.b64 P1, [%0], %1, 0x989680;\n\t" \
            "@P1 bra.uni D_%=;\n\t"                                                \
            "bra.uni W_%=;\n\t"                                                    \
            "D_%=:\n\t}" :: "r"(_m), "r"(_p) : "memory");                          \
    } } while (0)

#if TC_OK
#define MBAR_EXPECT(mbar, bytes) \
    asm volatile("mbarrier.arrive.expect_tx.shared.b64 _, [%0], %1;" \
                 :: "r"(mbar), "r"(bytes) : "memory")

#define TMA_LD2D(smem, tmapp, c0, c1, mbar) \
    asm volatile("cp.async.bulk.tensor.2d.shared::cta.global.tile.mbarrier::complete_tx::bytes " \
                 "[%0], [%1, {%2, %3}], [%4];" \
                 :: "r"(smem), "l"(tmapp), "r"(c0), "r"(c1), "r"(mbar) : "memory")

__device__ __forceinline__ void mma_tf32(uint32_t d, uint64_t ad, uint64_t bd,
                                         uint32_t idesc, bool acc) {
    uint32_t e = acc ? 1u : 0u;
    asm volatile(
        "{\n\t.reg .pred p;\n\tsetp.ne.u32 p, %5, 0;\n\t"
        "tcgen05.mma.cta_group::1.kind::tf32 [%0], %1, %2, %3, {%4, %4, %4, %4}, p;\n\t}"
        :: "r"(d), "l"(ad), "l"(bd), "r"(idesc), "r"(0u), "r"(e) : "memory");
}

__device__ __forceinline__ void mma_tf32_ts(uint32_t d, uint32_t a_tm, uint64_t bd,
                                            uint32_t idesc, bool acc) {
    uint32_t e = acc ? 1u : 0u;
    asm volatile(
        "{\n\t.reg .pred p;\n\tsetp.ne.u32 p, %5, 0;\n\t"
        "tcgen05.mma.cta_group::1.kind::tf32 [%0], [%1], %2, %3, {%4, %4, %4, %4}, p;\n\t}"
        :: "r"(d), "r"(a_tm), "l"(bd), "r"(idesc), "r"(0u), "r"(e) : "memory");
}

#define LDTM_X32(r, addr)                                                         \
    asm volatile("tcgen05.ld.sync.aligned.32x32b.x32.b32 "                        \
        "{%0, %1, %2, %3, %4, %5, %6, %7, %8, %9, %10, %11, %12, %13, %14, %15, " \
        " %16, %17, %18, %19, %20, %21, %22, %23, %24, %25, %26, %27, %28, %29, %30, %31}, [%32];" \
        : "=r"((r)[0]), "=r"((r)[1]), "=r"((r)[2]), "=r"((r)[3]),                 \
          "=r"((r)[4]), "=r"((r)[5]), "=r"((r)[6]), "=r"((r)[7]),                 \
          "=r"((r)[8]), "=r"((r)[9]), "=r"((r)[10]), "=r"((r)[11]),               \
          "=r"((r)[12]), "=r"((r)[13]), "=r"((r)[14]), "=r"((r)[15]),             \
          "=r"((r)[16]), "=r"((r)[17]), "=r"((r)[18]), "=r"((r)[19]),             \
          "=r"((r)[20]), "=r"((r)[21]), "=r"((r)[22]), "=r"((r)[23]),             \
          "=r"((r)[24]), "=r"((r)[25]), "=r"((r)[26]), "=r"((r)[27]),             \
          "=r"((r)[28]), "=r"((r)[29]), "=r"((r)[30]), "=r"((r)[31])              \
        : "r"(addr))

#define STTM_X32(addr, r)                                                         \
    asm volatile("tcgen05.st.sync.aligned.32x32b.x32.b32 [%0], "                  \
        "{%1, %2, %3, %4, %5, %6, %7, %8, %9, %10, %11, %12, %13, %14, %15, %16, "\
        " %17, %18, %19, %20, %21, %22, %23, %24, %25, %26, %27, %28, %29, %30, %31, %32};" \
        :: "r"(addr),                                                             \
           "r"((r)[0]), "r"((r)[1]), "r"((r)[2]), "r"((r)[3]),                    \
           "r"((r)[4]), "r"((r)[5]), "r"((r)[6]), "r"((r)[7]),                    \
           "r"((r)[8]), "r"((r)[9]), "r"((r)[10]), "r"((r)[11]),                  \
           "r"((r)[12]), "r"((r)[13]), "r"((r)[14]), "r"((r)[15]),                \
           "r"((r)[16]), "r"((r)[17]), "r"((r)[18]), "r"((r)[19]),                \
           "r"((r)[20]), "r"((r)[21]), "r"((r)[22]), "r"((r)[23]),                \
           "r"((r)[24]), "r"((r)[25]), "r"((r)[26]), "r"((r)[27]),                \
           "r"((r)[28]), "r"((r)[29]), "r"((r)[30]), "r"((r)[31])                 \
        : "memory")
#endif

static constexpr uint64_t DESC_BASE =
    (uint64_t(2) << 61) | (uint64_t(1) << 46) | (uint64_t(64) << 32) | (uint64_t(1) << 16);

// ---------------- merged prep: 4 weight transposes + input transpose ----------
__device__ __forceinline__ void wt_tile(const float* __restrict__ W, float* __restrict__ Wt,
                                        int R, int C, int bx, int by,
                                        int tx, int ty, float (*tile)[33]) {
    int c0 = bx * 32, r0 = by * 32;
    #pragma unroll
    for (int j = 0; j < 32; j += 8)
        tile[ty + j][tx] = W[(size_t)(r0 + ty + j) * C + c0 + tx];
    __syncthreads();
    #pragma unroll
    for (int j = 0; j < 32; j += 8)
        Wt[(size_t)(c0 + ty + j) * R + r0 + tx] = tile[tx][ty + j];
}

__global__ void k_prep(const float* __restrict__ W_qkv, float* __restrict__ wqkvT,
                       const float* __restrict__ W_proj, float* __restrict__ wprojT,
                       const float* __restrict__ W1, float* __restrict__ w1T,
                       const float* __restrict__ W2, float* __restrict__ w2T,
                       const float* __restrict__ x, float* __restrict__ t) {
    __shared__ float tile[32][33];
    int tx = threadIdx.x, ty = threadIdx.y;
    int idx = blockIdx.x;
    if (idx < 192) {            // wqkv: R=256, C=768, grid 24x8
        wt_tile(W_qkv, wqkvT, 256, 768, idx % 24, idx / 24, tx, ty, tile);
    } else if (idx < 256) {     // wproj: 8x8
        int i = idx - 192;
        wt_tile(W_proj, wprojT, 256, 256, i % 8, i / 8, tx, ty, tile);
    } else if (idx < 768) {     // w1: R=256, C=2048, grid 64x8
        int i = idx - 256;
        wt_tile(W1, w1T, 256, CMID, i % 64, i / 64, tx, ty, tile);
    } else if (idx < 1280) {    // w2: R=2048, C=256, grid 8x64
        int i = idx - 768;
        wt_tile(W2, w2T, CMID, 256, i % 8, i / 8, tx, ty, tile);
    } else {                    // in_transpose: 7 x 8 x 256
        int i = idx - 1280;
        int nx = i % 7, cy = (i / 7) % 8, b = i / 56;
        int n0 = nx * 32, c0 = cy * 32;
        const float* xb = x + (size_t)b * CC * NN;
        #pragma unroll
        for (int j = 0; j < 32; j += 8) {
            int c = c0 + ty + j, n = n0 + tx;
            if (n < NN) tile[ty + j][tx] = xb[(size_t)c * NN + n];
        }
        __syncthreads();
        #pragma unroll
        for (int j = 0; j < 32; j += 8) {
            int n = n0 + ty + j, c = c0 + tx;
            if (n < NN) t[((size_t)b * NN + n) * CC + c] = tile[tx][ty + j];
        }
    }
}

// ---------------- paired-tile tf32 GEMM: 2 x (128x128), epilogue overlap ------
// driver = tid 256 (warp 8): TMA+MMA chain over 2 passes (acc0 cols 0-127,
// acc1 cols 128-255), single-use done0/done1 commits.
// warps 0..7: drain acc0 while pass-1 mainloop runs, then acc1.
// epi 0: +bias ; 1: +bias,repbn(res+v) ; 2: +bias,SpatialSILU ;
// 3: +bias,repbn(res+v) -> [B,C,N]
__global__ __launch_bounds__(288)
void k_tgemm(const __grid_constant__ CUtensorMap tmA,
             const __grid_constant__ CUtensorMap tmB,
             const float* __restrict__ bias, float* __restrict__ out,
             int Nst, int K, int epi,
             const float* __restrict__ res,
             const float* __restrict__ gam, const float* __restrict__ bet,
             const float* __restrict__ rm,  const float* __restrict__ rv,
             const float* __restrict__ alpha,
             const float* __restrict__ saw, const float* __restrict__ sab)
{
#if TC_OK
    extern __shared__ char smem_raw[];
    __shared__ uint64_t s_mbar[6];   // full0, full1, empty0, empty1, done0, done1
    __shared__ uint32_t s_tmem;

    uint32_t sb_raw = smem_u32(smem_raw);
    uint32_t tbase = (sb_raw + 1023u) & ~1023u;
    char* tptr = smem_raw + (tbase - sb_raw);
    float* patbase = (float*)(tptr + 65536);

    int tid = threadIdx.x;
    int wid = tid >> 5, lid = tid & 31;
    int m0 = blockIdx.y * 128, n0 = blockIdx.x * 256;
    const int KC = K >> 5;
    const uint32_t IDESC = (1u << 4) | (2u << 7) | (2u << 10) | (16u << 17) | (8u << 24);

    if (wid == 0)
        asm volatile("tcgen05.alloc.cta_group::1.sync.aligned.shared::cta.b32 [%0], %1;"
                     :: "r"(smem_u32(&s_tmem)), "r"(256) : "memory");
    if (tid == 0)
        for (int i = 0; i < 6; i++) MBAR_INIT(smem_u32(&s_mbar[i]), 1);
    __syncthreads();
    uint32_t tmem = s_tmem;
    if (wid == 0)
        asm volatile("tcgen05.relinquish_alloc_permit.cta_group::1.sync.aligned;");

    uint32_t full[2]  = { smem_u32(&s_mbar[0]), smem_u32(&s_mbar[1]) };
    uint32_t empty[2] = { smem_u32(&s_mbar[2]), smem_u32(&s_mbar[3]) };
    uint32_t doneb[2] = { smem_u32(&s_mbar[4]), smem_u32(&s_mbar[5]) };

    if (tid == 256) {
        // ---- driver: continuous ring over 2*KC chunks ----
        int phf[2] = {0, 0}, phe[2] = {0, 0};
        const int TC2 = 2 * KC;
        #pragma unroll
        for (int p = 0; p < 2; p++) {     // chunks 0,1 (pass 0, kc 0,1; KC>=8)
            uint32_t sA = tbase + p * 32768, sB = sA + 16384;
            MBAR_EXPECT(full[p], 32768);
            TMA_LD2D(sA, &tmA, p * 32, m0, full[p]);
            TMA_LD2D(sB, &tmB, p * 32, n0, full[p]);
        }
        for (int c = 0; c < TC2; c++) {
            int buf = c & 1;
            int pass = (c >= KC) ? 1 : 0;
            int kc = c - pass * KC;
            uint32_t acc = tmem + pass * 128;
            uint32_t sA = tbase + buf * 32768, sB = sA + 16384;
            MBAR_WAIT(full[buf], phf[buf]); phf[buf] ^= 1;
            uint64_t ad = DESC_BASE | ((uint64_t)(sA >> 4) & 0x3FFF);
            uint64_t bd = DESC_BASE | ((uint64_t)(sB >> 4) & 0x3FFF);
            #pragma unroll
            for (int s = 0; s < 4; s++)
                mma_tf32(acc, ad + s * 2, bd + s * 2, IDESC, (kc > 0) || (s > 0));
            asm volatile(
                "tcgen05.commit.cta_group::1.mbarrier::arrive::one.shared::cluster.b64 [%0];"
                :: "r"(empty[buf]) : "memory");
            if (kc == KC - 1)
                asm volatile(
                    "tcgen05.commit.cta_group::1.mbarrier::arrive::one.shared::cluster.b64 [%0];"
                    :: "r"(doneb[pass]) : "memory");
            int nc = c + 2;
            if (nc < TC2) {
                MBAR_WAIT(empty[buf], phe[buf]); phe[buf] ^= 1;
                int np = (nc >= KC) ? 1 : 0;
                int nkc = nc - np * KC;
                MBAR_EXPECT(full[buf], 32768);
                TMA_LD2D(sA, &tmA, nkc * 32, m0, full[buf]);
                TMA_LD2D(sB, &tmB, nkc * 32, n0 + np * 128, full[buf]);
            }
        }
    } else if (tid < 256) {
        // ---- epilogue warps: drain acc0 then acc1 ----
        int sub = wid & 3, half = wid >> 2;
        float* spatch = patbase + wid * (32 * 33);
        int mrow = m0 + sub * 32;
        float alphav = (epi == 1 || epi == 3) ? alpha[0] : 0.f;
        int m_out = mrow + lid;
        int b_o = m_out / NN, nsp = m_out % NN;
        size_t obase = (size_t)b_o * CC * NN + nsp;
        for (int pass = 0; pass < 2; pass++) {
            MBAR_WAIT(doneb[pass], 0);
            asm volatile("tcgen05.fence::after_thread_sync;" ::: "memory");
            uint32_t acc = tmem + pass * 128;
            int n0p = n0 + pass * 128;
            #pragma unroll
            for (int cb = 0; cb < 2; cb++) {
                int c0 = half * 64 + cb * 32;
                uint32_t r[32];
                LDTM_X32(r, acc + c0);
                asm volatile("tcgen05.wait::ld.sync.aligned;" ::: "memory");
                #pragma unroll
                for (int j = 0; j < 32; j++) spatch[lid * 33 + j] = __uint_as_float(r[j]);
                __syncwarp();
                #pragma unroll
                for (int i = 0; i < 8; i++) {
                    int rr = i * 4 + (lid >> 3);
                    int c4 = (lid & 7) * 4;
                    int m = mrow + rr;
                    int n = n0p + c0 + c4;
                    float vv[4];
                    #pragma unroll
                    for (int e = 0; e < 4; e++) vv[e] = spatch[rr * 33 + c4 + e];
                    float4 bb = *(const float4*)(bias + n);
                    vv[0] += bb.x; vv[1] += bb.y; vv[2] += bb.z; vv[3] += bb.w;
                    if (epi == 1 || epi == 3) {
                        float4 r4 = *(const float4*)(res + (size_t)m * Nst + n);
                        float4 g4 = *(const float4*)(gam + n);
                        float4 b4 = *(const float4*)(bet + n);
                        float4 u4 = *(const float4*)(rm + n);
                        float4 s4 = *(const float4*)(rv + n);
                        float y;
                        y = r4.x + vv[0]; vv[0] = (y - u4.x) * (g4.x * rsqrtf(s4.x + EPSL)) + b4.x + alphav * y;
                        y = r4.y + vv[1]; vv[1] = (y - u4.y) * (g4.y * rsqrtf(s4.y + EPSL)) + b4.y + alphav * y;
                        y = r4.z + vv[2]; vv[2] = (y - u4.z) * (g4.z * rsqrtf(s4.z + EPSL)) + b4.z + alphav * y;
                        y = r4.w + vv[3]; vv[3] = (y - u4.w) * (g4.w * rsqrtf(s4.w + EPSL)) + b4.w + alphav * y;
                    } else if (epi == 2) {
                        float sw_ = saw[m / NN], sbv = sab[m / NN];
                        #pragma unroll
                        for (int e = 0; e < 4; e++) {
                            float w = sw_ * vv[e] + sbv;
                            vv[e] = vv[e] / (1.f + __expf(-w * vv[e]));
                        }
                    }
                    if (epi == 3) {
                        #pragma unroll
                        for (int e = 0; e < 4; e++) spatch[rr * 33 + c4 + e] = vv[e];
                    } else {
                        *(float4*)(out + (size_t)m * Nst + n) = make_float4(vv[0], vv[1], vv[2], vv[3]);
                    }
                }
                __syncwarp();
                if (epi == 3) {
                    #pragma unroll
                    for (int cc = 0; cc < 32; cc++)
                        out[obase + (size_t)(n0p + c0 + cc) * NN] = spatch[lid * 33 + cc];
                    __syncwarp();
                }
            }
        }
    }
    __syncthreads();
    if (tid == 0)
        for (int i = 0; i < 6; i++)
            asm volatile("mbarrier.inval.shared.b64 [%0];" :: "r"(smem_u32(&s_mbar[i])) : "memory");
    __syncthreads();
    if (wid == 0)
        asm volatile("tcgen05.dealloc.cta_group::1.sync.aligned.b32 %0, %1;"
                     :: "r"(tmem), "r"(256));
#endif
}

// ---------------- flash attention on tcgen05: block = (h, b) ------------------
__global__ __launch_bounds__(256)
void k_fattn(const __grid_constant__ CUtensorMap tmQKV,
             const float* __restrict__ qkv, float* __restrict__ attnout)
{
#if TC_OK
    extern __shared__ char smem_raw[];
    __shared__ uint64_t s_mbar[3];
    __shared__ uint32_t s_tmem;

    uint32_t sb_raw = smem_u32(smem_raw);
    uint32_t tbase = (sb_raw + 1023u) & ~1023u;
    char* tptr = smem_raw + (tbase - sb_raw);

    int tid = threadIdx.x, wid = tid >> 5, lid = tid & 31;
    int h = blockIdx.x, b = blockIdx.y;
    const uint32_t QOFF = 0, KOFF = 32768, VOFF = 61440;

    if (wid == 0)
        asm volatile("tcgen05.alloc.cta_group::1.sync.aligned.shared::cta.b32 [%0], %1;"
                     :: "r"(smem_u32(&s_tmem)), "r"(512) : "memory");
    if (tid == 0)
        for (int i = 0; i < 3; i++) MBAR_INIT(smem_u32(&s_mbar[i]), 1);
    __syncthreads();
    uint32_t tmem = s_tmem;
    if (wid == 0)
        asm volatile("tcgen05.relinquish_alloc_permit.cta_group::1.sync.aligned;");

    if (tid == 0) {
        MBAR_EXPECT(smem_u32(&s_mbar[0]), 2 * 196 * 128);
        TMA_LD2D(tbase + QOFF, &tmQKV, h * 32, b * 196, smem_u32(&s_mbar[0]));
        TMA_LD2D(tbase + KOFF, &tmQKV, 256 + h * 32, b * 196, smem_u32(&s_mbar[0]));
    }

    for (int i = tid; i < 1792; i += 256)
        ((float4*)(tptr + VOFF))[i] = make_float4(0.f, 0.f, 0.f, 0.f);
    __syncthreads();
    {
        size_t vbase = (size_t)b * 196 * 768 + 512 + (size_t)h * 32;
        for (int idx = tid; idx < 196 * 32; idx += 256) {
            int m = idx >> 5, d = idx & 31;
            float v = qkv[vbase + (size_t)m * 768 + d];
            int atom = (d >> 3) + (m >> 5) * 4;
            uint32_t bo = atom * 1024 + (d & 7) * 128 + (m & 31) * 4;
            uint32_t sw = bo ^ ((bo >> 3) & 0x70);
            *(float*)(tptr + VOFF + sw) = v;
        }
    }
    __syncthreads();

    const uint32_t IDESC1 = (1u << 4) | (2u << 7) | (2u << 10) | (28u << 17) | (8u << 24);
    const uint32_t IDESC2 = (1u << 4) | (2u << 7) | (2u << 10) | (4u << 17)  | (8u << 24);

    if (tid == 0) {
        MBAR_WAIT(smem_u32(&s_mbar[0]), 0);
        asm volatile("fence.proxy.async.shared::cta;" ::: "memory");
        uint64_t qd0 = DESC_BASE | ((uint64_t)((tbase + QOFF) >> 4) & 0x3FFF);
        uint64_t qd1 = DESC_BASE | ((uint64_t)((tbase + QOFF + 16384) >> 4) & 0x3FFF);
        uint64_t kd  = DESC_BASE | ((uint64_t)((tbase + KOFF) >> 4) & 0x3FFF);
        #pragma unroll
        for (int s = 0; s < 4; s++) mma_tf32(tmem,       qd0 + s * 2, kd + s * 2, IDESC1, s > 0);
        #pragma unroll
        for (int s = 0; s < 4; s++) mma_tf32(tmem + 224, qd1 + s * 2, kd + s * 2, IDESC1, s > 0);
        asm volatile(
            "tcgen05.commit.cta_group::1.mbarrier::arrive::one.shared::cluster.b64 [%0];"
            :: "r"(smem_u32(&s_mbar[1])) : "memory");
    }
    MBAR_WAIT(smem_u32(&s_mbar[1]), 0);
    asm volatile("tcgen05.fence::after_thread_sync;" ::: "memory");

    int sub = wid & 3, tile = wid >> 2;
    uint32_t Sbase = tmem + tile * 224;
    uint32_t stoff = (uint32_t)sub << 21;
    float l = 0.f;
    const float SC = 0.17677669529663687f;
    #pragma unroll
    for (int cb = 0; cb < 7; cb++) {
        uint32_t r[32];
        LDTM_X32(r, Sbase + cb * 32);
        asm volatile("tcgen05.wait::ld.sync.aligned;" ::: "memory");
        int vlim = (cb == 6) ? 4 : 32;
        #pragma unroll
        for (int j = 0; j < 32; j++) {
            float p = 0.f;
            if (j < vlim) { p = __expf(__uint_as_float(r[j]) * SC); l += p; }
            r[j] = __float_as_uint(p);
        }
        STTM_X32(Sbase + cb * 32 + stoff, r);
        asm volatile("tcgen05.wait::st.sync.aligned;" ::: "memory");
    }
    asm volatile("tcgen05.fence::before_thread_sync;" ::: "memory");
    __syncthreads();

    if (tid == 0) {
        asm volatile("tcgen05.fence::after_thread_sync;" ::: "memory");
        uint64_t vd = DESC_BASE | ((uint64_t)((tbase + VOFF) >> 4) & 0x3FFF);
        #pragma unroll
        for (int t = 0; t < 2; t++) {
            #pragma unroll
            for (int c = 0; c < 28; c++) {
                uint64_t bd = vd + (uint64_t)((c >> 2) * 256 + (c & 3) * 2);
                mma_tf32_ts(tmem + 448 + t * 32, tmem + t * 224 + c * 8, bd, IDESC2, c > 0);
            }
        }
        asm volatile(
            "tcgen05.commit.cta_group::1.mbarrier::arrive::one.shared::cluster.b64 [%0];"
            :: "r"(smem_u32(&s_mbar[2])) : "memory");
    }
    MBAR_WAIT(smem_u32(&s_mbar[2]), 0);
    asm volatile("tcgen05.fence::after_thread_sync;" ::: "memory");

    {
        uint32_t r[32];
        LDTM_X32(r, tmem + 448 + tile * 32);
        asm volatile("tcgen05.wait::ld.sync.aligned;" ::: "memory");
        int row = tile * 128 + sub * 32 + lid;
        if (row < 196) {
            float inv = 1.f / l;
            float* op = attnout + ((size_t)(b * NN + row)) * CC + h * 32;
            #pragma unroll
            for (int i = 0; i < 8; i++) {
                float4 o = make_float4(__uint_as_float(r[i*4+0]) * inv,
                                       __uint_as_float(r[i*4+1]) * inv,
                                       __uint_as_float(r[i*4+2]) * inv,
                                       __uint_as_float(r[i*4+3]) * inv);
                *(float4*)(op + i * 4) = o;
            }
        }
    }
    __syncthreads();
    if (tid == 0)
        for (int i = 0; i < 3; i++)
            asm volatile("mbarrier.inval.shared.b64 [%0];" :: "r"(smem_u32(&s_mbar[i])) : "memory");
    __syncthreads();
    if (wid == 0)
        asm volatile("tcgen05.dealloc.cta_group::1.sync.aligned.b32 %0, %1;"
                     :: "r"(tmem), "r"(512));
#endif
}

// ---------------- host: tensormap encode --------------------------------------
typedef CUresult (*PFN_encodeTiled)(
    CUtensorMap*, CUtensorMapDataType, cuuint32_t, void*,
    const cuuint64_t*, const cuuint64_t*, const cuuint32_t*, const cuuint32_t*,
    CUtensorMapInterleave, CUtensorMapSwizzle, CUtensorMapL2promotion,
    CUtensorMapFloatOOBfill);

static void encode_2d(PFN_encodeTiled enc, CUtensorMap* tm, void* base,
                      uint64_t rows, uint64_t cols, uint32_t box_rows) {
    cuuint64_t dims[2]    = { cols, rows };
    cuuint64_t strides[1] = { cols * 4 };
    cuuint32_t box[2]     = { 32, box_rows };
    cuuint32_t estr[2]    = { 1, 1 };
    enc(tm, CU_TENSOR_MAP_DATA_TYPE_FLOAT32, 2, base, dims, strides, box, estr,
        CU_TENSOR_MAP_INTERLEAVE_NONE, CU_TENSOR_MAP_SWIZZLE_128B,
        CU_TENSOR_MAP_L2_PROMOTION_L2_128B, CU_TENSOR_MAP_FLOAT_OOB_FILL_NONE);
}

// ---------------- launch ------------------------------------------------------
extern "C" void kernel_launch(void* const* d_in, const int* in_sizes, int n_in,
                              void* d_out, int out_size) {
    const float* x      = (const float*)d_in[0];
    const float* W_qkv  = (const float*)d_in[1];
    const float* b_qkv  = (const float*)d_in[2];
    const float* W_proj = (const float*)d_in[3];
    const float* b_proj = (const float*)d_in[4];
    const float* W1     = (const float*)d_in[5];
    const float* b1     = (const float*)d_in[6];
    const float* W2     = (const float*)d_in[7];
    const float* b2     = (const float*)d_in[8];
    const float* sa_w   = (const float*)d_in[9];
    const float* sa_b   = (const float*)d_in[10];
    const float* alpha1 = (const float*)d_in[11];
    const float* gamma1 = (const float*)d_in[12];
    const float* beta1  = (const float*)d_in[13];
    const float* rm1    = (const float*)d_in[14];
    const float* rv1    = (const float*)d_in[15];
    const float* alpha2 = (const float*)d_in[16];
    const float* gamma2 = (const float*)d_in[17];
    const float* beta2  = (const float*)d_in[18];
    const float* rm2    = (const float*)d_in[19];
    const float* rv2    = (const float*)d_in[20];
    float* out = (float*)d_out;

    float *t, *qkv, *attn, *t1, *hbuf, *wqkvT, *wprojT, *w1T, *w2T;
    cudaGetSymbolAddress((void**)&t,      g_t);
    cudaGetSymbolAddress((void**)&qkv,    g_qkv);
    cudaGetSymbolAddress((void**)&attn,   g_attn);
    cudaGetSymbolAddress((void**)&t1,     g_t1);
    cudaGetSymbolAddress((void**)&hbuf,   g_h);
    cudaGetSymbolAddress((void**)&wqkvT,  g_wqkvT);
    cudaGetSymbolAddress((void**)&wprojT, g_wprojT);
    cudaGetSymbolAddress((void**)&w1T,    g_w1T);
    cudaGetSymbolAddress((void**)&w2T,    g_w2T);

    void* fn = nullptr;
    cudaDriverEntryPointQueryResult qres;
    cudaGetDriverEntryPoint("cuTensorMapEncodeTiled", &fn, cudaEnableDefault, &qres);
    PFN_encodeTiled enc = (PFN_encodeTiled)fn;

    CUtensorMap tm_t, tm_wqkv, tm_attn, tm_wproj, tm_t1, tm_w1, tm_h, tm_w2, tm_qa;
    encode_2d(enc, &tm_t,     t,      MM,   256,  128);
    encode_2d(enc, &tm_wqkv,  wqkvT,  768,  256,  128);
    encode_2d(enc, &tm_attn,  attn,   MM,   256,  128);
    encode_2d(enc, &tm_wproj, wprojT, 256,  256,  128);
    encode_2d(enc, &tm_t1,    t1,     MM,   256,  128);
    encode_2d(enc, &tm_w1,    w1T,    CMID, 256,  128);
    encode_2d(enc, &tm_h,     hbuf,   MM,   CMID, 128);
    encode_2d(enc, &tm_w2,    w2T,    256,  CMID, 128);
    encode_2d(enc, &tm_qa,    qkv,    MM,   768,  196);

    const int GEMM_SMEM = 1024 + 2 * 32768 + 8 * 32 * 33 * 4;   // 100352
    const int FATT_SMEM = 1024 + 32768 + 28672 + 28672;         // 91136
    cudaFuncSetAttribute(k_tgemm, cudaFuncAttributeMaxDynamicSharedMemorySize, GEMM_SMEM);
    cudaFuncSetAttribute(k_fattn, cudaFuncAttributeMaxDynamicSharedMemorySize, FATT_SMEM);

    dim3 tb(32, 8);
    // merged prep: 4 weight transposes + input transpose (1280 + 14336 blocks)
    k_prep<<<15616, tb>>>(W_qkv, wqkvT, W_proj, wprojT, W1, w1T, W2, w2T, x, t);
    // QKV: 3 tile-pairs x 392
    k_tgemm<<<dim3(3, MM / 128), 288, GEMM_SMEM>>>(tm_t, tm_wqkv, b_qkv, qkv,
        768, 256, 0, nullptr, nullptr, nullptr, nullptr, nullptr, nullptr, nullptr, nullptr);
    // flash attention on tensor cores
    k_fattn<<<dim3(8, BB), 256, FATT_SMEM>>>(tm_qa, qkv, attn);
    // proj + residual + repbn1: 1 pair x 392
    k_tgemm<<<dim3(1, MM / 128), 288, GEMM_SMEM>>>(tm_attn, tm_wproj, b_proj, t1,
        256, 256, 1, t, gamma1, beta1, rm1, rv1, alpha1, nullptr, nullptr);
    // FFN1 + SpatialSILU: 8 pairs x 392
    k_tgemm<<<dim3(8, MM / 128), 288, GEMM_SMEM>>>(tm_t1, tm_w1, b1, hbuf,
        CMID, 256, 2, nullptr, nullptr, nullptr, nullptr, nullptr, nullptr, sa_w, sa_b);
    // FFN2 + residual + repbn2 -> [B,C,N]: 1 pair x 392, K=2048
    k_tgemm<<<dim3(1, MM / 128), 288, GEMM_SMEM>>>(tm_h, tm_w2, b2, out,
        256, CMID, 3, t1, gamma2, beta2, rm2, rv2, alpha2, nullptr, nullptr);
}

// round 16
// speedup vs baseline: 1.7251x; 1.7251x over previous
#include <cuda_runtime.h>
#include <cuda.h>
#include <cstdint>
#include <math.h>

#define BB 256
#define CC 256
#define NN 196
#define MM (BB*NN)        // 50176
#define CMID 2048
#define EPSL 1e-5f

#if defined(__CUDA_ARCH_FEAT_SM103_ALL) || defined(__CUDA_ARCH_FEAT_SM100_ALL) || defined(__CUDA_ARCH_FEAT_SM101_ALL)
#define TC_OK 1
#else
#define TC_OK 0
#endif

// ---------------- scratch (device globals) -----------------------------------
__device__ float g_t   [(size_t)MM*CC];
__device__ float g_qkv [(size_t)MM*3*CC];
__device__ float g_attn[(size_t)MM*CC];
__device__ float g_t1  [(size_t)MM*CC];
__device__ float g_h   [(size_t)MM*CMID];
__device__ float g_wqkvT[(size_t)3*CC*CC];   // [768,256]
__device__ float g_wprojT[(size_t)CC*CC];    // [256,256]
__device__ float g_w1T  [(size_t)CMID*CC];   // [2048,256]
__device__ float g_w2T  [(size_t)CC*CMID];   // [256,2048]

// ---------------- PTX helpers -------------------------------------------------
__device__ __forceinline__ uint32_t smem_u32(const void* p) {
    uint32_t a;
    asm("{ .reg .u64 t; cvta.to.shared.u64 t, %1; cvt.u32.u64 %0, t; }" : "=r"(a) : "l"(p));
    return a;
}

#define MBAR_INIT(addr, cnt) \
    asm volatile("mbarrier.init.shared.b64 [%0], %1;" :: "r"(addr), "r"(cnt) : "memory")

#define MBAR_WAIT(addr, parity) do {                                              \
    uint32_t _m = (addr); uint32_t _p = (parity); uint32_t _d;                    \
    asm volatile("{\n\t.reg .pred p;\n\t"                                         \
        "mbarrier.try_wait.parity.acquire.cta.shared::cta.b64 p, [%1], %2;\n\t"   \
        "selp.b32 %0, 1, 0, p;\n\t}" : "=r"(_d) : "r"(_m), "r"(_p) : "memory");   \
    if (!_d) {                                                                     \
        asm volatile("{\n\t.reg .pred P1;\n\t"                                     \
            "W_%=:\n\t"                                                            \
            "mbarrier.try_wait.parity.acquire.cta.shared::cta.b64 P1, [%0], %1, 0x989680;\n\t" \
            "@P1 bra.uni D_%=;\n\t"                                                \
            "bra.uni W_%=;\n\t"                                                    \
            "D_%=:\n\t}" :: "r"(_m), "r"(_p) : "memory");                          \
    } } while (0)

#if TC_OK
#define MBAR_EXPECT(mbar, bytes) \
    asm volatile("mbarrier.arrive.expect_tx.shared.b64 _, [%0], %1;" \
                 :: "r"(mbar), "r"(bytes) : "memory")

#define TMA_LD2D(smem, tmapp, c0, c1, mbar) \
    asm volatile("cp.async.bulk.tensor.2d.shared::cta.global.tile.mbarrier::complete_tx::bytes " \
                 "[%0], [%1, {%2, %3}], [%4];" \
                 :: "r"(smem), "l"(tmapp), "r"(c0), "r"(c1), "r"(mbar) : "memory")

__device__ __forceinline__ void mma_tf32(uint32_t d, uint64_t ad, uint64_t bd,
                                         uint32_t idesc, bool acc) {
    uint32_t e = acc ? 1u : 0u;
    asm volatile(
        "{\n\t.reg .pred p;\n\tsetp.ne.u32 p, %5, 0;\n\t"
        "tcgen05.mma.cta_group::1.kind::tf32 [%0], %1, %2, %3, {%4, %4, %4, %4}, p;\n\t}"
        :: "r"(d), "l"(ad), "l"(bd), "r"(idesc), "r"(0u), "r"(e) : "memory");
}

__device__ __forceinline__ void mma_tf32_ts(uint32_t d, uint32_t a_tm, uint64_t bd,
                                            uint32_t idesc, bool acc) {
    uint32_t e = acc ? 1u : 0u;
    asm volatile(
        "{\n\t.reg .pred p;\n\tsetp.ne.u32 p, %5, 0;\n\t"
        "tcgen05.mma.cta_group::1.kind::tf32 [%0], [%1], %2, %3, {%4, %4, %4, %4}, p;\n\t}"
        :: "r"(d), "r"(a_tm), "l"(bd), "r"(idesc), "r"(0u), "r"(e) : "memory");
}

#define LDTM_X32(r, addr)                                                         \
    asm volatile("tcgen05.ld.sync.aligned.32x32b.x32.b32 "                        \
        "{%0, %1, %2, %3, %4, %5, %6, %7, %8, %9, %10, %11, %12, %13, %14, %15, " \
        " %16, %17, %18, %19, %20, %21, %22, %23, %24, %25, %26, %27, %28, %29, %30, %31}, [%32];" \
        : "=r"((r)[0]), "=r"((r)[1]), "=r"((r)[2]), "=r"((r)[3]),                 \
          "=r"((r)[4]), "=r"((r)[5]), "=r"((r)[6]), "=r"((r)[7]),                 \
          "=r"((r)[8]), "=r"((r)[9]), "=r"((r)[10]), "=r"((r)[11]),               \
          "=r"((r)[12]), "=r"((r)[13]), "=r"((r)[14]), "=r"((r)[15]),             \
          "=r"((r)[16]), "=r"((r)[17]), "=r"((r)[18]), "=r"((r)[19]),             \
          "=r"((r)[20]), "=r"((r)[21]), "=r"((r)[22]), "=r"((r)[23]),             \
          "=r"((r)[24]), "=r"((r)[25]), "=r"((r)[26]), "=r"((r)[27]),             \
          "=r"((r)[28]), "=r"((r)[29]), "=r"((r)[30]), "=r"((r)[31])              \
        : "r"(addr))

#define STTM_X32(addr, r)                                                         \
    asm volatile("tcgen05.st.sync.aligned.32x32b.x32.b32 [%0], "                  \
        "{%1, %2, %3, %4, %5, %6, %7, %8, %9, %10, %11, %12, %13, %14, %15, %16, "\
        " %17, %18, %19, %20, %21, %22, %23, %24, %25, %26, %27, %28, %29, %30, %31, %32};" \
        :: "r"(addr),                                                             \
           "r"((r)[0]), "r"((r)[1]), "r"((r)[2]), "r"((r)[3]),                    \
           "r"((r)[4]), "r"((r)[5]), "r"((r)[6]), "r"((r)[7]),                    \
           "r"((r)[8]), "r"((r)[9]), "r"((r)[10]), "r"((r)[11]),                  \
           "r"((r)[12]), "r"((r)[13]), "r"((r)[14]), "r"((r)[15]),                \
           "r"((r)[16]), "r"((r)[17]), "r"((r)[18]), "r"((r)[19]),                \
           "r"((r)[20]), "r"((r)[21]), "r"((r)[22]), "r"((r)[23]),                \
           "r"((r)[24]), "r"((r)[25]), "r"((r)[26]), "r"((r)[27]),                \
           "r"((r)[28]), "r"((r)[29]), "r"((r)[30]), "r"((r)[31])                 \
        : "memory")
#endif

static constexpr uint64_t DESC_BASE =
    (uint64_t(2) << 61) | (uint64_t(1) << 46) | (uint64_t(64) << 32) | (uint64_t(1) << 16);

// ---------------- merged prep: 4 weight transposes + input transpose ----------
__device__ __forceinline__ void wt_tile(const float* __restrict__ W, float* __restrict__ Wt,
                                        int R, int C, int bx, int by,
                                        int tx, int ty, float (*tile)[33]) {
    int c0 = bx * 32, r0 = by * 32;
    #pragma unroll
    for (int j = 0; j < 32; j += 8)
        tile[ty + j][tx] = W[(size_t)(r0 + ty + j) * C + c0 + tx];
    __syncthreads();
    #pragma unroll
    for (int j = 0; j < 32; j += 8)
        Wt[(size_t)(c0 + ty + j) * R + r0 + tx] = tile[tx][ty + j];
}

__global__ void k_prep(const float* __restrict__ W_qkv, float* __restrict__ wqkvT,
                       const float* __restrict__ W_proj, float* __restrict__ wprojT,
                       const float* __restrict__ W1, float* __restrict__ w1T,
                       const float* __restrict__ W2, float* __restrict__ w2T,
                       const float* __restrict__ x, float* __restrict__ t) {
    __shared__ float tile[32][33];
    int tx = threadIdx.x, ty = threadIdx.y;
    int idx = blockIdx.x;
    if (idx < 192) {            // wqkv: R=256, C=768, grid 24x8
        wt_tile(W_qkv, wqkvT, 256, 768, idx % 24, idx / 24, tx, ty, tile);
    } else if (idx < 256) {     // wproj: 8x8
        int i = idx - 192;
        wt_tile(W_proj, wprojT, 256, 256, i % 8, i / 8, tx, ty, tile);
    } else if (idx < 768) {     // w1: R=256, C=2048, grid 64x8
        int i = idx - 256;
        wt_tile(W1, w1T, 256, CMID, i % 64, i / 64, tx, ty, tile);
    } else if (idx < 1280) {    // w2: R=2048, C=256, grid 8x64
        int i = idx - 768;
        wt_tile(W2, w2T, CMID, 256, i % 8, i / 8, tx, ty, tile);
    } else {                    // in_transpose: 7 x 8 x 256
        int i = idx - 1280;
        int nx = i % 7, cy = (i / 7) % 8, b = i / 56;
        int n0 = nx * 32, c0 = cy * 32;
        const float* xb = x + (size_t)b * CC * NN;
        #pragma unroll
        for (int j = 0; j < 32; j += 8) {
            int c = c0 + ty + j, n = n0 + tx;
            if (n < NN) tile[ty + j][tx] = xb[(size_t)c * NN + n];
        }
        __syncthreads();
        #pragma unroll
        for (int j = 0; j < 32; j += 8) {
            int n = n0 + ty + j, c = c0 + tx;
            if (n < NN) t[((size_t)b * NN + n) * CC + c] = tile[tx][ty + j];
        }
    }
}

// ---------------- TMA tcgen05 tf32 GEMM 128x128: out = A @ Bt^T + epilogue ----
// epi 0: +bias ; epi 1: +bias, repbn(res+v) ; epi 2: +bias, SpatialSILU
__global__ __launch_bounds__(256)
void k_tgemm(const __grid_constant__ CUtensorMap tmA,
             const __grid_constant__ CUtensorMap tmB,
             const float* __restrict__ bias, float* __restrict__ out,
             int N, int K, int epi,
             const float* __restrict__ res,
             const float* __restrict__ gam, const float* __restrict__ bet,
             const float* __restrict__ rm,  const float* __restrict__ rv,
             const float* __restrict__ alpha,
             const float* __restrict__ saw, const float* __restrict__ sab)
{
#if TC_OK
    extern __shared__ char smem_raw[];
    __shared__ uint64_t s_mbar[5];   // full0, full1, empty0, empty1, done
    __shared__ uint32_t s_tmem;

    uint32_t sb_raw = smem_u32(smem_raw);
    uint32_t tbase = (sb_raw + 1023u) & ~1023u;
    char* tptr = smem_raw + (tbase - sb_raw);

    int tid = threadIdx.x;
    int wid = tid >> 5, lid = tid & 31;
    int m0 = blockIdx.y * 128, n0 = blockIdx.x * 128;

    if (wid == 0)
        asm volatile("tcgen05.alloc.cta_group::1.sync.aligned.shared::cta.b32 [%0], %1;"
                     :: "r"(smem_u32(&s_tmem)), "r"(128) : "memory");
    if (tid == 0)
        for (int i = 0; i < 5; i++) MBAR_INIT(smem_u32(&s_mbar[i]), 1);
    __syncthreads();
    uint32_t tmem = s_tmem;
    if (wid == 0)
        asm volatile("tcgen05.relinquish_alloc_permit.cta_group::1.sync.aligned;");

    const uint32_t IDESC = (1u << 4) | (2u << 7) | (2u << 10) | (16u << 17) | (8u << 24);
    const int KC = K >> 5;

    if (tid == 0) {
        uint32_t full[2]  = { smem_u32(&s_mbar[0]), smem_u32(&s_mbar[1]) };
        uint32_t empty[2] = { smem_u32(&s_mbar[2]), smem_u32(&s_mbar[3]) };
        int phf[2] = {0, 0}, phe[2] = {0, 0};
        #pragma unroll
        for (int p = 0; p < 2; p++) {
            uint32_t sA = tbase + p * 32768, sB = sA + 16384;
            MBAR_EXPECT(full[p], 32768);
            TMA_LD2D(sA, &tmA, p * 32, m0, full[p]);
            TMA_LD2D(sB, &tmB, p * 32, n0, full[p]);
        }
        for (int kc = 0; kc < KC; kc++) {
            int buf = kc & 1;
            uint32_t sA = tbase + buf * 32768, sB = sA + 16384;
            MBAR_WAIT(full[buf], phf[buf]); phf[buf] ^= 1;
            uint64_t ad = DESC_BASE | ((uint64_t)(sA >> 4) & 0x3FFF);
            uint64_t bd = DESC_BASE | ((uint64_t)(sB >> 4) & 0x3FFF);
            #pragma unroll
            for (int s = 0; s < 4; s++)
                mma_tf32(tmem, ad + s * 2, bd + s * 2, IDESC, (kc > 0) || (s > 0));
            asm volatile(
                "tcgen05.commit.cta_group::1.mbarrier::arrive::one.shared::cluster.b64 [%0];"
                :: "r"(empty[buf]) : "memory");
            if (kc + 2 < KC) {
                MBAR_WAIT(empty[buf], phe[buf]); phe[buf] ^= 1;
                MBAR_EXPECT(full[buf], 32768);
                TMA_LD2D(sA, &tmA, (kc + 2) * 32, m0, full[buf]);
                TMA_LD2D(sB, &tmB, (kc + 2) * 32, n0, full[buf]);
            }
        }
        asm volatile(
            "tcgen05.commit.cta_group::1.mbarrier::arrive::one.shared::cluster.b64 [%0];"
            :: "r"(smem_u32(&s_mbar[4])) : "memory");
    }
    MBAR_WAIT(smem_u32(&s_mbar[4]), 0);
    asm volatile("tcgen05.fence::after_thread_sync;" ::: "memory");
    __syncthreads();

    // ---- 8-warp coalesced epilogue ----
    {
        int sub = wid & 3, half = wid >> 2;
        float* spatch = (float*)tptr + wid * (32 * 33);
        int mrow = m0 + sub * 32;
        float alphav = (epi == 1) ? alpha[0] : 0.f;
        #pragma unroll
        for (int cb = 0; cb < 2; cb++) {
            int c0 = half * 64 + cb * 32;
            uint32_t r[32];
            LDTM_X32(r, tmem + c0);
            asm volatile("tcgen05.wait::ld.sync.aligned;" ::: "memory");
            #pragma unroll
            for (int j = 0; j < 32; j++) spatch[lid * 33 + j] = __uint_as_float(r[j]);
            __syncwarp();
            #pragma unroll
            for (int i = 0; i < 8; i++) {
                int rr = i * 4 + (lid >> 3);
                int c4 = (lid & 7) * 4;
                int m = mrow + rr;
                int n = n0 + c0 + c4;
                float vv[4];
                #pragma unroll
                for (int e = 0; e < 4; e++) vv[e] = spatch[rr * 33 + c4 + e];
                float4 bb = *(const float4*)(bias + n);
                vv[0] += bb.x; vv[1] += bb.y; vv[2] += bb.z; vv[3] += bb.w;
                if (epi == 1) {
                    float4 r4 = *(const float4*)(res + (size_t)m * N + n);
                    float4 g4 = *(const float4*)(gam + n);
                    float4 b4 = *(const float4*)(bet + n);
                    float4 u4 = *(const float4*)(rm + n);
                    float4 s4 = *(const float4*)(rv + n);
                    float y;
                    y = r4.x + vv[0]; vv[0] = (y - u4.x) * (g4.x * rsqrtf(s4.x + EPSL)) + b4.x + alphav * y;
                    y = r4.y + vv[1]; vv[1] = (y - u4.y) * (g4.y * rsqrtf(s4.y + EPSL)) + b4.y + alphav * y;
                    y = r4.z + vv[2]; vv[2] = (y - u4.z) * (g4.z * rsqrtf(s4.z + EPSL)) + b4.z + alphav * y;
                    y = r4.w + vv[3]; vv[3] = (y - u4.w) * (g4.w * rsqrtf(s4.w + EPSL)) + b4.w + alphav * y;
                } else if (epi == 2) {
                    int bidx = m / NN;
                    float sw_ = saw[bidx], sbv = sab[bidx];
                    #pragma unroll
                    for (int e = 0; e < 4; e++) {
                        float w = sw_ * vv[e] + sbv;
                        vv[e] = vv[e] / (1.f + __expf(-w * vv[e]));
                    }
                }
                *(float4*)(out + (size_t)m * N + n) = make_float4(vv[0], vv[1], vv[2], vv[3]);
            }
            __syncwarp();
        }
    }
    __syncthreads();
    if (tid == 0)
        for (int i = 0; i < 5; i++)
            asm volatile("mbarrier.inval.shared.b64 [%0];" :: "r"(smem_u32(&s_mbar[i])) : "memory");
    __syncthreads();
    if (wid == 0)
        asm volatile("tcgen05.dealloc.cta_group::1.sync.aligned.b32 %0, %1;"
                     :: "r"(tmem), "r"(128));
#endif
}

// ---------------- TMA wide GEMM 128x256 (FFN2): single hbuf read, BCN out -----
__global__ __launch_bounds__(256)
void k_tgemm_w(const __grid_constant__ CUtensorMap tmA,
               const __grid_constant__ CUtensorMap tmB,
               const float* __restrict__ bias, float* __restrict__ out,
               int K,
               const float* __restrict__ res,
               const float* __restrict__ gam, const float* __restrict__ bet,
               const float* __restrict__ rm,  const float* __restrict__ rv,
               const float* __restrict__ alpha)
{
#if TC_OK
    extern __shared__ char smem_raw[];
    __shared__ uint64_t s_mbar[5];
    __shared__ uint32_t s_tmem;

    uint32_t sb_raw = smem_u32(smem_raw);
    uint32_t tbase = (sb_raw + 1023u) & ~1023u;
    char* tptr = smem_raw + (tbase - sb_raw);

    int tid = threadIdx.x;
    int wid = tid >> 5, lid = tid & 31;
    int m0 = blockIdx.x * 128;
    const int N = 256;

    if (wid == 0)
        asm volatile("tcgen05.alloc.cta_group::1.sync.aligned.shared::cta.b32 [%0], %1;"
                     :: "r"(smem_u32(&s_tmem)), "r"(256) : "memory");
    if (tid == 0)
        for (int i = 0; i < 5; i++) MBAR_INIT(smem_u32(&s_mbar[i]), 1);
    __syncthreads();
    uint32_t tmem = s_tmem;
    if (wid == 0)
        asm volatile("tcgen05.relinquish_alloc_permit.cta_group::1.sync.aligned;");

    const uint32_t IDESC = (1u << 4) | (2u << 7) | (2u << 10) | (32u << 17) | (8u << 24);
    const int KC = K >> 5;

    if (tid == 0) {
        uint32_t full[2]  = { smem_u32(&s_mbar[0]), smem_u32(&s_mbar[1]) };
        uint32_t empty[2] = { smem_u32(&s_mbar[2]), smem_u32(&s_mbar[3]) };
        int phf[2] = {0, 0}, phe[2] = {0, 0};
        #pragma unroll
        for (int p = 0; p < 2; p++) {
            uint32_t sA = tbase + p * 49152, sB = sA + 16384;
            MBAR_EXPECT(full[p], 49152);
            TMA_LD2D(sA, &tmA, p * 32, m0, full[p]);
            TMA_LD2D(sB, &tmB, p * 32, 0, full[p]);
        }
        for (int kc = 0; kc < KC; kc++) {
            int buf = kc & 1;
            uint32_t sA = tbase + buf * 49152, sB = sA + 16384;
            MBAR_WAIT(full[buf], phf[buf]); phf[buf] ^= 1;
            uint64_t ad = DESC_BASE | ((uint64_t)(sA >> 4) & 0x3FFF);
            uint64_t bd = DESC_BASE | ((uint64_t)(sB >> 4) & 0x3FFF);
            #pragma unroll
            for (int s = 0; s < 4; s++)
                mma_tf32(tmem, ad + s * 2, bd + s * 2, IDESC, (kc > 0) || (s > 0));
            asm volatile(
                "tcgen05.commit.cta_group::1.mbarrier::arrive::one.shared::cluster.b64 [%0];"
                :: "r"(empty[buf]) : "memory");
            if (kc + 2 < KC) {
                MBAR_WAIT(empty[buf], phe[buf]); phe[buf] ^= 1;
                MBAR_EXPECT(full[buf], 49152);
                TMA_LD2D(sA, &tmA, (kc + 2) * 32, m0, full[buf]);
                TMA_LD2D(sB, &tmB, (kc + 2) * 32, 0, full[buf]);
            }
        }
        asm volatile(
            "tcgen05.commit.cta_group::1.mbarrier::arrive::one.shared::cluster.b64 [%0];"
            :: "r"(smem_u32(&s_mbar[4])) : "memory");
    }
    MBAR_WAIT(smem_u32(&s_mbar[4]), 0);
    asm volatile("tcgen05.fence::after_thread_sync;" ::: "memory");
    __syncthreads();

    // 8-warp epilogue -> [B,C,N]
    {
        int sub = wid & 3, half = wid >> 2;
        float* spatch = (float*)tptr + wid * (32 * 33);
        int mrow = m0 + sub * 32;
        float alphav = alpha[0];
        int m_out = mrow + lid;
        int b_o = m_out / NN, nsp = m_out % NN;
        size_t obase = (size_t)b_o * CC * NN + nsp;
        #pragma unroll
        for (int cb = 0; cb < 4; cb++) {
            int c0 = half * 128 + cb * 32;
            uint32_t r[32];
            LDTM_X32(r, tmem + c0);
            asm volatile("tcgen05.wait::ld.sync.aligned;" ::: "memory");
            #pragma unroll
            for (int j = 0; j < 32; j++) spatch[lid * 33 + j] = __uint_as_float(r[j]);
            __syncwarp();
            #pragma unroll
            for (int i = 0; i < 8; i++) {
                int rr = i * 4 + (lid >> 3);
                int c4 = (lid & 7) * 4;
                int m = mrow + rr;
                int n = c0 + c4;
                float vv[4];
                #pragma unroll
                for (int e = 0; e < 4; e++) vv[e] = spatch[rr * 33 + c4 + e];
                float4 bb = *(const float4*)(bias + n);
                float4 r4 = *(const float4*)(res + (size_t)m * N + n);
                float4 g4 = *(const float4*)(gam + n);
                float4 b4 = *(const float4*)(bet + n);
                float4 u4 = *(const float4*)(rm + n);
                float4 s4 = *(const float4*)(rv + n);
                float y;
                y = r4.x + vv[0] + bb.x; vv[0] = (y - u4.x) * (g4.x * rsqrtf(s4.x + EPSL)) + b4.x + alphav * y;
                y = r4.y + vv[1] + bb.y; vv[1] = (y - u4.y) * (g4.y * rsqrtf(s4.y + EPSL)) + b4.y + alphav * y;
                y = r4.z + vv[2] + bb.z; vv[2] = (y - u4.z) * (g4.z * rsqrtf(s4.z + EPSL)) + b4.z + alphav * y;
                y = r4.w + vv[3] + bb.w; vv[3] = (y - u4.w) * (g4.w * rsqrtf(s4.w + EPSL)) + b4.w + alphav * y;
                #pragma unroll
                for (int e = 0; e < 4; e++) spatch[rr * 33 + c4 + e] = vv[e];
            }
            __syncwarp();
            #pragma unroll
            for (int cc = 0; cc < 32; cc++)
                out[obase + (size_t)(c0 + cc) * NN] = spatch[lid * 33 + cc];
            __syncwarp();
        }
    }
    __syncthreads();
    if (tid == 0)
        for (int i = 0; i < 5; i++)
            asm volatile("mbarrier.inval.shared.b64 [%0];" :: "r"(smem_u32(&s_mbar[i])) : "memory");
    __syncthreads();
    if (wid == 0)
        asm volatile("tcgen05.dealloc.cta_group::1.sync.aligned.b32 %0, %1;"
                     :: "r"(tmem), "r"(256));
#endif
}

// ---------------- flash attention on tcgen05: block = (h, b) ------------------
__global__ __launch_bounds__(256)
void k_fattn(const __grid_constant__ CUtensorMap tmQKV,
             const float* __restrict__ qkv, float* __restrict__ attnout)
{
#if TC_OK
    extern __shared__ char smem_raw[];
    __shared__ uint64_t s_mbar[3];
    __shared__ uint32_t s_tmem;

    uint32_t sb_raw = smem_u32(smem_raw);
    uint32_t tbase = (sb_raw + 1023u) & ~1023u;
    char* tptr = smem_raw + (tbase - sb_raw);

    int tid = threadIdx.x, wid = tid >> 5, lid = tid & 31;
    int h = blockIdx.x, b = blockIdx.y;
    const uint32_t QOFF = 0, KOFF = 32768, VOFF = 61440;

    if (wid == 0)
        asm volatile("tcgen05.alloc.cta_group::1.sync.aligned.shared::cta.b32 [%0], %1;"
                     :: "r"(smem_u32(&s_tmem)), "r"(512) : "memory");
    if (tid == 0)
        for (int i = 0; i < 3; i++) MBAR_INIT(smem_u32(&s_mbar[i]), 1);
    __syncthreads();
    uint32_t tmem = s_tmem;
    if (wid == 0)
        asm volatile("tcgen05.relinquish_alloc_permit.cta_group::1.sync.aligned;");

    if (tid == 0) {
        MBAR_EXPECT(smem_u32(&s_mbar[0]), 2 * 196 * 128);
        TMA_LD2D(tbase + QOFF, &tmQKV, h * 32, b * 196, smem_u32(&s_mbar[0]));
        TMA_LD2D(tbase + KOFF, &tmQKV, 256 + h * 32, b * 196, smem_u32(&s_mbar[0]));
    }

    for (int i = tid; i < 1792; i += 256)
        ((float4*)(tptr + VOFF))[i] = make_float4(0.f, 0.f, 0.f, 0.f);
    __syncthreads();
    {
        size_t vbase = (size_t)b * 196 * 768 + 512 + (size_t)h * 32;
        for (int idx = tid; idx < 196 * 32; idx += 256) {
            int m = idx >> 5, d = idx & 31;
            float v = qkv[vbase + (size_t)m * 768 + d];
            int atom = (d >> 3) + (m >> 5) * 4;
            uint32_t bo = atom * 1024 + (d & 7) * 128 + (m & 31) * 4;
            uint32_t sw = bo ^ ((bo >> 3) & 0x70);
            *(float*)(tptr + VOFF + sw) = v;
        }
    }
    __syncthreads();

    const uint32_t IDESC1 = (1u << 4) | (2u << 7) | (2u << 10) | (28u << 17) | (8u << 24);
    const uint32_t IDESC2 = (1u << 4) | (2u << 7) | (2u << 10) | (4u << 17)  | (8u << 24);

    if (tid == 0) {
        MBAR_WAIT(smem_u32(&s_mbar[0]), 0);
        asm volatile("fence.proxy.async.shared::cta;" ::: "memory");
        uint64_t qd0 = DESC_BASE | ((uint64_t)((tbase + QOFF) >> 4) & 0x3FFF);
        uint64_t qd1 = DESC_BASE | ((uint64_t)((tbase + QOFF + 16384) >> 4) & 0x3FFF);
        uint64_t kd  = DESC_BASE | ((uint64_t)((tbase + KOFF) >> 4) & 0x3FFF);
        #pragma unroll
        for (int s = 0; s < 4; s++) mma_tf32(tmem,       qd0 + s * 2, kd + s * 2, IDESC1, s > 0);
        #pragma unroll
        for (int s = 0; s < 4; s++) mma_tf32(tmem + 224, qd1 + s * 2, kd + s * 2, IDESC1, s > 0);
        asm volatile(
            "tcgen05.commit.cta_group::1.mbarrier::arrive::one.shared::cluster.b64 [%0];"
            :: "r"(smem_u32(&s_mbar[1])) : "memory");
    }
    MBAR_WAIT(smem_u32(&s_mbar[1]), 0);
    asm volatile("tcgen05.fence::after_thread_sync;" ::: "memory");

    int sub = wid & 3, tile = wid >> 2;
    uint32_t Sbase = tmem + tile * 224;
    uint32_t stoff = (uint32_t)sub << 21;
    float l = 0.f;
    const float SC = 0.17677669529663687f;
    #pragma unroll
    for (int cb = 0; cb < 7; cb++) {
        uint32_t r[32];
        LDTM_X32(r, Sbase + cb * 32);
        asm volatile("tcgen05.wait::ld.sync.aligned;" ::: "memory");
        int vlim = (cb == 6) ? 4 : 32;
        #pragma unroll
        for (int j = 0; j < 32; j++) {
            float p = 0.f;
            if (j < vlim) { p = __expf(__uint_as_float(r[j]) * SC); l += p; }
            r[j] = __float_as_uint(p);
        }
        STTM_X32(Sbase + cb * 32 + stoff, r);
        asm volatile("tcgen05.wait::st.sync.aligned;" ::: "memory");
    }
    asm volatile("tcgen05.fence::before_thread_sync;" ::: "memory");
    __syncthreads();

    if (tid == 0) {
        asm volatile("tcgen05.fence::after_thread_sync;" ::: "memory");
        uint64_t vd = DESC_BASE | ((uint64_t)((tbase + VOFF) >> 4) & 0x3FFF);
        #pragma unroll
        for (int t = 0; t < 2; t++) {
            #pragma unroll
            for (int c = 0; c < 28; c++) {
                uint64_t bd = vd + (uint64_t)((c >> 2) * 256 + (c & 3) * 2);
                mma_tf32_ts(tmem + 448 + t * 32, tmem + t * 224 + c * 8, bd, IDESC2, c > 0);
            }
        }
        asm volatile(
            "tcgen05.commit.cta_group::1.mbarrier::arrive::one.shared::cluster.b64 [%0];"
            :: "r"(smem_u32(&s_mbar[2])) : "memory");
    }
    MBAR_WAIT(smem_u32(&s_mbar[2]), 0);
    asm volatile("tcgen05.fence::after_thread_sync;" ::: "memory");

    {
        uint32_t r[32];
        LDTM_X32(r, tmem + 448 + tile * 32);
        asm volatile("tcgen05.wait::ld.sync.aligned;" ::: "memory");
        int row = tile * 128 + sub * 32 + lid;
        if (row < 196) {
            float inv = 1.f / l;
            float* op = attnout + ((size_t)(b * NN + row)) * CC + h * 32;
            #pragma unroll
            for (int i = 0; i < 8; i++) {
                float4 o = make_float4(__uint_as_float(r[i*4+0]) * inv,
                                       __uint_as_float(r[i*4+1]) * inv,
                                       __uint_as_float(r[i*4+2]) * inv,
                                       __uint_as_float(r[i*4+3]) * inv);
                *(float4*)(op + i * 4) = o;
            }
        }
    }
    __syncthreads();
    if (tid == 0)
        for (int i = 0; i < 3; i++)
            asm volatile("mbarrier.inval.shared.b64 [%0];" :: "r"(smem_u32(&s_mbar[i])) : "memory");
    __syncthreads();
    if (wid == 0)
        asm volatile("tcgen05.dealloc.cta_group::1.sync.aligned.b32 %0, %1;"
                     :: "r"(tmem), "r"(512));
#endif
}

// ---------------- host: tensormap encode --------------------------------------
typedef CUresult (*PFN_encodeTiled)(
    CUtensorMap*, CUtensorMapDataType, cuuint32_t, void*,
    const cuuint64_t*, const cuuint64_t*, const cuuint32_t*, const cuuint32_t*,
    CUtensorMapInterleave, CUtensorMapSwizzle, CUtensorMapL2promotion,
    CUtensorMapFloatOOBfill);

static void encode_2d(PFN_encodeTiled enc, CUtensorMap* tm, void* base,
                      uint64_t rows, uint64_t cols, uint32_t box_rows) {
    cuuint64_t dims[2]    = { cols, rows };
    cuuint64_t strides[1] = { cols * 4 };
    cuuint32_t box[2]     = { 32, box_rows };
    cuuint32_t estr[2]    = { 1, 1 };
    enc(tm, CU_TENSOR_MAP_DATA_TYPE_FLOAT32, 2, base, dims, strides, box, estr,
        CU_TENSOR_MAP_INTERLEAVE_NONE, CU_TENSOR_MAP_SWIZZLE_128B,
        CU_TENSOR_MAP_L2_PROMOTION_L2_128B, CU_TENSOR_MAP_FLOAT_OOB_FILL_NONE);
}

// ---------------- launch ------------------------------------------------------
extern "C" void kernel_launch(void* const* d_in, const int* in_sizes, int n_in,
                              void* d_out, int out_size) {
    const float* x      = (const float*)d_in[0];
    const float* W_qkv  = (const float*)d_in[1];
    const float* b_qkv  = (const float*)d_in[2];
    const float* W_proj = (const float*)d_in[3];
    const float* b_proj = (const float*)d_in[4];
    const float* W1     = (const float*)d_in[5];
    const float* b1     = (const float*)d_in[6];
    const float* W2     = (const float*)d_in[7];
    const float* b2     = (const float*)d_in[8];
    const float* sa_w   = (const float*)d_in[9];
    const float* sa_b   = (const float*)d_in[10];
    const float* alpha1 = (const float*)d_in[11];
    const float* gamma1 = (const float*)d_in[12];
    const float* beta1  = (const float*)d_in[13];
    const float* rm1    = (const float*)d_in[14];
    const float* rv1    = (const float*)d_in[15];
    const float* alpha2 = (const float*)d_in[16];
    const float* gamma2 = (const float*)d_in[17];
    const float* beta2  = (const float*)d_in[18];
    const float* rm2    = (const float*)d_in[19];
    const float* rv2    = (const float*)d_in[20];
    float* out = (float*)d_out;

    float *t, *qkv, *attn, *t1, *hbuf, *wqkvT, *wprojT, *w1T, *w2T;
    cudaGetSymbolAddress((void**)&t,      g_t);
    cudaGetSymbolAddress((void**)&qkv,    g_qkv);
    cudaGetSymbolAddress((void**)&attn,   g_attn);
    cudaGetSymbolAddress((void**)&t1,     g_t1);
    cudaGetSymbolAddress((void**)&hbuf,   g_h);
    cudaGetSymbolAddress((void**)&wqkvT,  g_wqkvT);
    cudaGetSymbolAddress((void**)&wprojT, g_wprojT);
    cudaGetSymbolAddress((void**)&w1T,    g_w1T);
    cudaGetSymbolAddress((void**)&w2T,    g_w2T);

    void* fn = nullptr;
    cudaDriverEntryPointQueryResult qres;
    cudaGetDriverEntryPoint("cuTensorMapEncodeTiled", &fn, cudaEnableDefault, &qres);
    PFN_encodeTiled enc = (PFN_encodeTiled)fn;

    CUtensorMap tm_t, tm_wqkv, tm_attn, tm_wproj, tm_t1, tm_w1, tm_h, tm_w2, tm_qa;
    encode_2d(enc, &tm_t,     t,      MM,   256,  128);
    encode_2d(enc, &tm_wqkv,  wqkvT,  768,  256,  128);
    encode_2d(enc, &tm_attn,  attn,   MM,   256,  128);
    encode_2d(enc, &tm_wproj, wprojT, 256,  256,  128);
    encode_2d(enc, &tm_t1,    t1,     MM,   256,  128);
    encode_2d(enc, &tm_w1,    w1T,    CMID, 256,  128);
    encode_2d(enc, &tm_h,     hbuf,   MM,   CMID, 128);
    encode_2d(enc, &tm_w2,    w2T,    256,  CMID, 256);
    encode_2d(enc, &tm_qa,    qkv,    MM,   768,  196);

    const int GEMM_SMEM  = 1024 + 2 * 32768;              // 66560
    const int GEMMW_SMEM = 1024 + 2 * 49152;              // 99328
    const int FATT_SMEM  = 1024 + 32768 + 28672 + 28672;  // 91136
    cudaFuncSetAttribute(k_tgemm,   cudaFuncAttributeMaxDynamicSharedMemorySize, GEMM_SMEM);
    cudaFuncSetAttribute(k_tgemm_w, cudaFuncAttributeMaxDynamicSharedMemorySize, GEMMW_SMEM);
    cudaFuncSetAttribute(k_fattn,   cudaFuncAttributeMaxDynamicSharedMemorySize, FATT_SMEM);

    dim3 tb(32, 8);
    // merged prep: 4 weight transposes + input transpose
    k_prep<<<15616, tb>>>(W_qkv, wqkvT, W_proj, wprojT, W1, w1T, W2, w2T, x, t);
    // QKV
    k_tgemm<<<dim3(768 / 128, MM / 128), 256, GEMM_SMEM>>>(tm_t, tm_wqkv, b_qkv, qkv,
        768, 256, 0, nullptr, nullptr, nullptr, nullptr, nullptr, nullptr, nullptr, nullptr);
    // flash attention on tensor cores
    k_fattn<<<dim3(8, BB), 256, FATT_SMEM>>>(tm_qa, qkv, attn);
    // proj + residual + repbn1
    k_tgemm<<<dim3(256 / 128, MM / 128), 256, GEMM_SMEM>>>(tm_attn, tm_wproj, b_proj, t1,
        256, 256, 1, t, gamma1, beta1, rm1, rv1, alpha1, nullptr, nullptr);
    // FFN1 + SpatialSILU
    k_tgemm<<<dim3(CMID / 128, MM / 128), 256, GEMM_SMEM>>>(tm_t1, tm_w1, b1, hbuf,
        CMID, 256, 2, nullptr, nullptr, nullptr, nullptr, nullptr, nullptr, sa_w, sa_b);
    // FFN2 (wide) + residual + repbn2 -> [B,C,N]
    k_tgemm_w<<<MM / 128, 256, GEMMW_SMEM>>>(tm_h, tm_w2, b2, out,
        CMID, t1, gamma2, beta2, rm2, rv2, alpha2);
}

// round 17
// speedup vs baseline: 1.9341x; 1.1211x over previous
#include <cuda_runtime.h>
#include <cuda.h>
#include <cuda_bf16.h>
#include <cstdint>
#include <math.h>

#define BB 256
#define CC 256
#define NN 196
#define MM (BB*NN)        // 50176
#define CMID 2048
#define EPSL 1e-5f

#if defined(__CUDA_ARCH_FEAT_SM103_ALL) || defined(__CUDA_ARCH_FEAT_SM100_ALL) || defined(__CUDA_ARCH_FEAT_SM101_ALL)
#define TC_OK 1
#else
#define TC_OK 0
#endif

// ---------------- scratch (device globals) -----------------------------------
__device__ float g_t   [(size_t)MM*CC];
__device__ float g_qkv [(size_t)MM*3*CC];
__device__ float g_attn[(size_t)MM*CC];
__device__ float g_t1  [(size_t)MM*CC];
__device__ __nv_bfloat16 g_h [(size_t)MM*CMID];      // bf16 FFN intermediate
__device__ float g_wqkvT[(size_t)3*CC*CC];           // [768,256]
__device__ float g_wprojT[(size_t)CC*CC];            // [256,256]
__device__ float g_w1T  [(size_t)CMID*CC];           // [2048,256]
__device__ __nv_bfloat16 g_w2T[(size_t)CC*CMID];     // [256,2048] bf16

// ---------------- PTX helpers -------------------------------------------------
__device__ __forceinline__ uint32_t smem_u32(const void* p) {
    uint32_t a;
    asm("{ .reg .u64 t; cvta.to.shared.u64 t, %1; cvt.u32.u64 %0, t; }" : "=r"(a) : "l"(p));
    return a;
}

#define MBAR_INIT(addr, cnt) \
    asm volatile("mbarrier.init.shared.b64 [%0], %1;" :: "r"(addr), "r"(cnt) : "memory")

#define MBAR_WAIT(addr, parity) do {                                              \
    uint32_t _m = (addr); uint32_t _p = (parity); uint32_t _d;                    \
    asm volatile("{\n\t.reg .pred p;\n\t"                                         \
        "mbarrier.try_wait.parity.acquire.cta.shared::cta.b64 p, [%1], %2;\n\t"   \
        "selp.b32 %0, 1, 0, p;\n\t}" : "=r"(_d) : "r"(_m), "r"(_p) : "memory");   \
    if (!_d) {                                                                     \
        asm volatile("{\n\t.reg .pred P1;\n\t"                                     \
            "W_%=:\n\t"                                                            \
            "mbarrier.try_wait.parity.acquire.cta.shared::cta.b64 P1, [%0], %1, 0x989680;\n\t" \
            "@P1 bra.uni D_%=;\n\t"                                                \
            "bra.uni W_%=;\n\t"                                                    \
            "D_%=:\n\t}" :: "r"(_m), "r"(_p) : "memory");                          \
    } } while (0)

#if TC_OK
#define MBAR_EXPECT(mbar, bytes) \
    asm volatile("mbarrier.arrive.expect_tx.shared.b64 _, [%0], %1;" \
                 :: "r"(mbar), "r"(bytes) : "memory")

#define TMA_LD2D(smem, tmapp, c0, c1, mbar) \
    asm volatile("cp.async.bulk.tensor.2d.shared::cta.global.tile.mbarrier::complete_tx::bytes " \
                 "[%0], [%1, {%2, %3}], [%4];" \
                 :: "r"(smem), "l"(tmapp), "r"(c0), "r"(c1), "r"(mbar) : "memory")

__device__ __forceinline__ void mma_tf32(uint32_t d, uint64_t ad, uint64_t bd,
                                         uint32_t idesc, bool acc) {
    uint32_t e = acc ? 1u : 0u;
    asm volatile(
        "{\n\t.reg .pred p;\n\tsetp.ne.u32 p, %5, 0;\n\t"
        "tcgen05.mma.cta_group::1.kind::tf32 [%0], %1, %2, %3, {%4, %4, %4, %4}, p;\n\t}"
        :: "r"(d), "l"(ad), "l"(bd), "r"(idesc), "r"(0u), "r"(e) : "memory");
}

__device__ __forceinline__ void mma_f16(uint32_t d, uint64_t ad, uint64_t bd,
                                        uint32_t idesc, bool acc) {
    uint32_t e = acc ? 1u : 0u;
    asm volatile(
        "{\n\t.reg .pred p;\n\tsetp.ne.u32 p, %5, 0;\n\t"
        "tcgen05.mma.cta_group::1.kind::f16 [%0], %1, %2, %3, {%4, %4, %4, %4}, p;\n\t}"
        :: "r"(d), "l"(ad), "l"(bd), "r"(idesc), "r"(0u), "r"(e) : "memory");
}

__device__ __forceinline__ void mma_tf32_ts(uint32_t d, uint32_t a_tm, uint64_t bd,
                                            uint32_t idesc, bool acc) {
    uint32_t e = acc ? 1u : 0u;
    asm volatile(
        "{\n\t.reg .pred p;\n\tsetp.ne.u32 p, %5, 0;\n\t"
        "tcgen05.mma.cta_group::1.kind::tf32 [%0], [%1], %2, %3, {%4, %4, %4, %4}, p;\n\t}"
        :: "r"(d), "r"(a_tm), "l"(bd), "r"(idesc), "r"(0u), "r"(e) : "memory");
}

#define LDTM_X32(r, addr)                                                         \
    asm volatile("tcgen05.ld.sync.aligned.32x32b.x32.b32 "                        \
        "{%0, %1, %2, %3, %4, %5, %6, %7, %8, %9, %10, %11, %12, %13, %14, %15, " \
        " %16, %17, %18, %19, %20, %21, %22, %23, %24, %25, %26, %27, %28, %29, %30, %31}, [%32];" \
        : "=r"((r)[0]), "=r"((r)[1]), "=r"((r)[2]), "=r"((r)[3]),                 \
          "=r"((r)[4]), "=r"((r)[5]), "=r"((r)[6]), "=r"((r)[7]),                 \
          "=r"((r)[8]), "=r"((r)[9]), "=r"((r)[10]), "=r"((r)[11]),               \
          "=r"((r)[12]), "=r"((r)[13]), "=r"((r)[14]), "=r"((r)[15]),             \
          "=r"((r)[16]), "=r"((r)[17]), "=r"((r)[18]), "=r"((r)[19]),             \
          "=r"((r)[20]), "=r"((r)[21]), "=r"((r)[22]), "=r"((r)[23]),             \
          "=r"((r)[24]), "=r"((r)[25]), "=r"((r)[26]), "=r"((r)[27]),             \
          "=r"((r)[28]), "=r"((r)[29]), "=r"((r)[30]), "=r"((r)[31])              \
        : "r"(addr))

#define STTM_X32(addr, r)                                                         \
    asm volatile("tcgen05.st.sync.aligned.32x32b.x32.b32 [%0], "                  \
        "{%1, %2, %3, %4, %5, %6, %7, %8, %9, %10, %11, %12, %13, %14, %15, %16, "\
        " %17, %18, %19, %20, %21, %22, %23, %24, %25, %26, %27, %28, %29, %30, %31, %32};" \
        :: "r"(addr),                                                             \
           "r"((r)[0]), "r"((r)[1]), "r"((r)[2]), "r"((r)[3]),                    \
           "r"((r)[4]), "r"((r)[5]), "r"((r)[6]), "r"((r)[7]),                    \
           "r"((r)[8]), "r"((r)[9]), "r"((r)[10]), "r"((r)[11]),                  \
           "r"((r)[12]), "r"((r)[13]), "r"((r)[14]), "r"((r)[15]),                \
           "r"((r)[16]), "r"((r)[17]), "r"((r)[18]), "r"((r)[19]),                \
           "r"((r)[20]), "r"((r)[21]), "r"((r)[22]), "r"((r)[23]),                \
           "r"((r)[24]), "r"((r)[25]), "r"((r)[26]), "r"((r)[27]),                \
           "r"((r)[28]), "r"((r)[29]), "r"((r)[30]), "r"((r)[31])                 \
        : "memory")
#endif

static constexpr uint64_t DESC_BASE =
    (uint64_t(2) << 61) | (uint64_t(1) << 46) | (uint64_t(64) << 32) | (uint64_t(1) << 16);

// ---------------- merged prep: weight transposes (+bf16 W2) + input transpose -
__device__ __forceinline__ void wt_tile(const float* __restrict__ W, float* __restrict__ Wt,
                                        int R, int C, int bx, int by,
                                        int tx, int ty, float (*tile)[33]) {
    int c0 = bx * 32, r0 = by * 32;
    #pragma unroll
    for (int j = 0; j < 32; j += 8)
        tile[ty + j][tx] = W[(size_t)(r0 + ty + j) * C + c0 + tx];
    __syncthreads();
    #pragma unroll
    for (int j = 0; j < 32; j += 8)
        Wt[(size_t)(c0 + ty + j) * R + r0 + tx] = tile[tx][ty + j];
}

__global__ void k_prep(const float* __restrict__ W_qkv, float* __restrict__ wqkvT,
                       const float* __restrict__ W_proj, float* __restrict__ wprojT,
                       const float* __restrict__ W1, float* __restrict__ w1T,
                       const float* __restrict__ W2, __nv_bfloat16* __restrict__ w2T,
                       const float* __restrict__ x, float* __restrict__ t) {
    __shared__ float tile[32][33];
    int tx = threadIdx.x, ty = threadIdx.y;
    int idx = blockIdx.x;
    if (idx < 192) {            // wqkv: R=256, C=768, grid 24x8
        wt_tile(W_qkv, wqkvT, 256, 768, idx % 24, idx / 24, tx, ty, tile);
    } else if (idx < 256) {     // wproj: 8x8
        int i = idx - 192;
        wt_tile(W_proj, wprojT, 256, 256, i % 8, i / 8, tx, ty, tile);
    } else if (idx < 768) {     // w1: R=256, C=2048, grid 64x8
        int i = idx - 256;
        wt_tile(W1, w1T, 256, CMID, i % 64, i / 64, tx, ty, tile);
    } else if (idx < 1280) {    // w2 -> bf16: R=2048, C=256, grid 8x64
        int i = idx - 768;
        int bx = i % 8, by = i / 8;
        int c0 = bx * 32, r0 = by * 32;
        #pragma unroll
        for (int j = 0; j < 32; j += 8)
            tile[ty + j][tx] = W2[(size_t)(r0 + ty + j) * 256 + c0 + tx];
        __syncthreads();
        #pragma unroll
        for (int j = 0; j < 32; j += 8)
            w2T[(size_t)(c0 + ty + j) * CMID + r0 + tx] = __float2bfloat16(tile[tx][ty + j]);
    } else {                    // in_transpose: 7 x 8 x 256
        int i = idx - 1280;
        int nx = i % 7, cy = (i / 7) % 8, b = i / 56;
        int n0 = nx * 32, c0 = cy * 32;
        const float* xb = x + (size_t)b * CC * NN;
        #pragma unroll
        for (int j = 0; j < 32; j += 8) {
            int c = c0 + ty + j, n = n0 + tx;
            if (n < NN) tile[ty + j][tx] = xb[(size_t)c * NN + n];
        }
        __syncthreads();
        #pragma unroll
        for (int j = 0; j < 32; j += 8) {
            int n = n0 + ty + j, c = c0 + tx;
            if (n < NN) t[((size_t)b * NN + n) * CC + c] = tile[tx][ty + j];
        }
    }
}

// ---------------- TMA tcgen05 tf32 GEMM 128x128: out = A @ Bt^T + epilogue ----
// epi 0: +bias ; epi 1: +bias, repbn(res+v) ; epi 2: +bias, SpatialSILU -> bf16
__global__ __launch_bounds__(256)
void k_tgemm(const __grid_constant__ CUtensorMap tmA,
             const __grid_constant__ CUtensorMap tmB,
             const float* __restrict__ bias, float* __restrict__ out,
             int N, int K, int epi,
             const float* __restrict__ res,
             const float* __restrict__ gam, const float* __restrict__ bet,
             const float* __restrict__ rm,  const float* __restrict__ rv,
             const float* __restrict__ alpha,
             const float* __restrict__ saw, const float* __restrict__ sab)
{
#if TC_OK
    extern __shared__ char smem_raw[];
    __shared__ uint64_t s_mbar[5];   // full0, full1, empty0, empty1, done
    __shared__ uint32_t s_tmem;

    uint32_t sb_raw = smem_u32(smem_raw);
    uint32_t tbase = (sb_raw + 1023u) & ~1023u;
    char* tptr = smem_raw + (tbase - sb_raw);

    int tid = threadIdx.x;
    int wid = tid >> 5, lid = tid & 31;
    int m0 = blockIdx.y * 128, n0 = blockIdx.x * 128;

    if (wid == 0)
        asm volatile("tcgen05.alloc.cta_group::1.sync.aligned.shared::cta.b32 [%0], %1;"
                     :: "r"(smem_u32(&s_tmem)), "r"(128) : "memory");
    if (tid == 0)
        for (int i = 0; i < 5; i++) MBAR_INIT(smem_u32(&s_mbar[i]), 1);
    __syncthreads();
    uint32_t tmem = s_tmem;
    if (wid == 0)
        asm volatile("tcgen05.relinquish_alloc_permit.cta_group::1.sync.aligned;");

    const uint32_t IDESC = (1u << 4) | (2u << 7) | (2u << 10) | (16u << 17) | (8u << 24);
    const int KC = K >> 5;

    if (tid == 0) {
        uint32_t full[2]  = { smem_u32(&s_mbar[0]), smem_u32(&s_mbar[1]) };
        uint32_t empty[2] = { smem_u32(&s_mbar[2]), smem_u32(&s_mbar[3]) };
        int phf[2] = {0, 0}, phe[2] = {0, 0};
        #pragma unroll
        for (int p = 0; p < 2; p++) {
            uint32_t sA = tbase + p * 32768, sB = sA + 16384;
            MBAR_EXPECT(full[p], 32768);
            TMA_LD2D(sA, &tmA, p * 32, m0, full[p]);
            TMA_LD2D(sB, &tmB, p * 32, n0, full[p]);
        }
        for (int kc = 0; kc < KC; kc++) {
            int buf = kc & 1;
            uint32_t sA = tbase + buf * 32768, sB = sA + 16384;
            MBAR_WAIT(full[buf], phf[buf]); phf[buf] ^= 1;
            uint64_t ad = DESC_BASE | ((uint64_t)(sA >> 4) & 0x3FFF);
            uint64_t bd = DESC_BASE | ((uint64_t)(sB >> 4) & 0x3FFF);
            #pragma unroll
            for (int s = 0; s < 4; s++)
                mma_tf32(tmem, ad + s * 2, bd + s * 2, IDESC, (kc > 0) || (s > 0));
            asm volatile(
                "tcgen05.commit.cta_group::1.mbarrier::arrive::one.shared::cluster.b64 [%0];"
                :: "r"(empty[buf]) : "memory");
            if (kc + 2 < KC) {
                MBAR_WAIT(empty[buf], phe[buf]); phe[buf] ^= 1;
                MBAR_EXPECT(full[buf], 32768);
                TMA_LD2D(sA, &tmA, (kc + 2) * 32, m0, full[buf]);
                TMA_LD2D(sB, &tmB, (kc + 2) * 32, n0, full[buf]);
            }
        }
        asm volatile(
            "tcgen05.commit.cta_group::1.mbarrier::arrive::one.shared::cluster.b64 [%0];"
            :: "r"(smem_u32(&s_mbar[4])) : "memory");
    }
    MBAR_WAIT(smem_u32(&s_mbar[4]), 0);
    asm volatile("tcgen05.fence::after_thread_sync;" ::: "memory");
    __syncthreads();

    // ---- 8-warp coalesced epilogue ----
    {
        int sub = wid & 3, half = wid >> 2;
        float* spatch = (float*)tptr + wid * (32 * 33);
        int mrow = m0 + sub * 32;
        float alphav = (epi == 1) ? alpha[0] : 0.f;
        #pragma unroll
        for (int cb = 0; cb < 2; cb++) {
            int c0 = half * 64 + cb * 32;
            uint32_t r[32];
            LDTM_X32(r, tmem + c0);
            asm volatile("tcgen05.wait::ld.sync.aligned;" ::: "memory");
            #pragma unroll
            for (int j = 0; j < 32; j++) spatch[lid * 33 + j] = __uint_as_float(r[j]);
            __syncwarp();
            #pragma unroll
            for (int i = 0; i < 8; i++) {
                int rr = i * 4 + (lid >> 3);
                int c4 = (lid & 7) * 4;
                int m = mrow + rr;
                int n = n0 + c0 + c4;
                float vv[4];
                #pragma unroll
                for (int e = 0; e < 4; e++) vv[e] = spatch[rr * 33 + c4 + e];
                float4 bb = *(const float4*)(bias + n);
                vv[0] += bb.x; vv[1] += bb.y; vv[2] += bb.z; vv[3] += bb.w;
                if (epi == 1) {
                    float4 r4 = *(const float4*)(res + (size_t)m * N + n);
                    float4 g4 = *(const float4*)(gam + n);
                    float4 b4 = *(const float4*)(bet + n);
                    float4 u4 = *(const float4*)(rm + n);
                    float4 s4 = *(const float4*)(rv + n);
                    float y;
                    y = r4.x + vv[0]; vv[0] = (y - u4.x) * (g4.x * rsqrtf(s4.x + EPSL)) + b4.x + alphav * y;
                    y = r4.y + vv[1]; vv[1] = (y - u4.y) * (g4.y * rsqrtf(s4.y + EPSL)) + b4.y + alphav * y;
                    y = r4.z + vv[2]; vv[2] = (y - u4.z) * (g4.z * rsqrtf(s4.z + EPSL)) + b4.z + alphav * y;
                    y = r4.w + vv[3]; vv[3] = (y - u4.w) * (g4.w * rsqrtf(s4.w + EPSL)) + b4.w + alphav * y;
                    *(float4*)(out + (size_t)m * N + n) = make_float4(vv[0], vv[1], vv[2], vv[3]);
                } else if (epi == 2) {
                    int bidx = m / NN;
                    float sw_ = saw[bidx], sbv = sab[bidx];
                    #pragma unroll
                    for (int e = 0; e < 4; e++) {
                        float w = sw_ * vv[e] + sbv;
                        vv[e] = vv[e] / (1.f + __expf(-w * vv[e]));
                    }
                    uint32_t p0, p1;
                    asm("cvt.rn.bf16x2.f32 %0, %1, %2;" : "=r"(p0) : "f"(vv[1]), "f"(vv[0]));
                    asm("cvt.rn.bf16x2.f32 %0, %1, %2;" : "=r"(p1) : "f"(vv[3]), "f"(vv[2]));
                    __nv_bfloat16* ob = (__nv_bfloat16*)out;
                    *(uint2*)(ob + (size_t)m * N + n) = make_uint2(p0, p1);
                } else {
                    *(float4*)(out + (size_t)m * N + n) = make_float4(vv[0], vv[1], vv[2], vv[3]);
                }
            }
            __syncwarp();
        }
    }
    __syncthreads();
    if (tid == 0)
        for (int i = 0; i < 5; i++)
            asm volatile("mbarrier.inval.shared.b64 [%0];" :: "r"(smem_u32(&s_mbar[i])) : "memory");
    __syncthreads();
    if (wid == 0)
        asm volatile("tcgen05.dealloc.cta_group::1.sync.aligned.b32 %0, %1;"
                     :: "r"(tmem), "r"(128));
#endif
}

// ---------------- bf16 wide GEMM 128x256 (FFN2): h bf16 @ W2 bf16, BCN out ----
__global__ __launch_bounds__(256)
void k_tgemm_w(const __grid_constant__ CUtensorMap tmA,
               const __grid_constant__ CUtensorMap tmB,
               const float* __restrict__ bias, float* __restrict__ out,
               int K,
               const float* __restrict__ res,
               const float* __restrict__ gam, const float* __restrict__ bet,
               const float* __restrict__ rm,  const float* __restrict__ rv,
               const float* __restrict__ alpha)
{
#if TC_OK
    extern __shared__ char smem_raw[];
    __shared__ uint64_t s_mbar[5];
    __shared__ uint32_t s_tmem;

    uint32_t sb_raw = smem_u32(smem_raw);
    uint32_t tbase = (sb_raw + 1023u) & ~1023u;
    char* tptr = smem_raw + (tbase - sb_raw);

    int tid = threadIdx.x;
    int wid = tid >> 5, lid = tid & 31;
    int m0 = blockIdx.x * 128;
    const int N = 256;

    if (wid == 0)
        asm volatile("tcgen05.alloc.cta_group::1.sync.aligned.shared::cta.b32 [%0], %1;"
                     :: "r"(smem_u32(&s_tmem)), "r"(256) : "memory");
    if (tid == 0)
        for (int i = 0; i < 5; i++) MBAR_INIT(smem_u32(&s_mbar[i]), 1);
    __syncthreads();
    uint32_t tmem = s_tmem;
    if (wid == 0)
        asm volatile("tcgen05.relinquish_alloc_permit.cta_group::1.sync.aligned;");

    // bf16 kind::f16: dtype F32, atype/btype BF16, N=256, M=128
    const uint32_t IDESC = (1u << 4) | (1u << 7) | (1u << 10) | (32u << 17) | (8u << 24);
    const int KC = K >> 6;    // 64 bf16 elements per chunk (128B rows)

    if (tid == 0) {
        uint32_t full[2]  = { smem_u32(&s_mbar[0]), smem_u32(&s_mbar[1]) };
        uint32_t empty[2] = { smem_u32(&s_mbar[2]), smem_u32(&s_mbar[3]) };
        int phf[2] = {0, 0}, phe[2] = {0, 0};
        #pragma unroll
        for (int p = 0; p < 2; p++) {
            uint32_t sA = tbase + p * 49152, sB = sA + 16384;
            MBAR_EXPECT(full[p], 49152);
            TMA_LD2D(sA, &tmA, p * 64, m0, full[p]);
            TMA_LD2D(sB, &tmB, p * 64, 0, full[p]);
        }
        for (int kc = 0; kc < KC; kc++) {
            int buf = kc & 1;
            uint32_t sA = tbase + buf * 49152, sB = sA + 16384;
            MBAR_WAIT(full[buf], phf[buf]); phf[buf] ^= 1;
            uint64_t ad = DESC_BASE | ((uint64_t)(sA >> 4) & 0x3FFF);
            uint64_t bd = DESC_BASE | ((uint64_t)(sB >> 4) & 0x3FFF);
            #pragma unroll
            for (int s = 0; s < 4; s++)       // 4 x K=16 bf16 steps (32B = 2 units)
                mma_f16(tmem, ad + s * 2, bd + s * 2, IDESC, (kc > 0) || (s > 0));
            asm volatile(
                "tcgen05.commit.cta_group::1.mbarrier::arrive::one.shared::cluster.b64 [%0];"
                :: "r"(empty[buf]) : "memory");
            if (kc + 2 < KC) {
                MBAR_WAIT(empty[buf], phe[buf]); phe[buf] ^= 1;
                MBAR_EXPECT(full[buf], 49152);
                TMA_LD2D(sA, &tmA, (kc + 2) * 64, m0, full[buf]);
                TMA_LD2D(sB, &tmB, (kc + 2) * 64, 0, full[buf]);
            }
        }
        asm volatile(
            "tcgen05.commit.cta_group::1.mbarrier::arrive::one.shared::cluster.b64 [%0];"
            :: "r"(smem_u32(&s_mbar[4])) : "memory");
    }
    MBAR_WAIT(smem_u32(&s_mbar[4]), 0);
    asm volatile("tcgen05.fence::after_thread_sync;" ::: "memory");
    __syncthreads();

    // 8-warp epilogue -> [B,C,N]
    {
        int sub = wid & 3, half = wid >> 2;
        float* spatch = (float*)tptr + wid * (32 * 33);
        int mrow = m0 + sub * 32;
        float alphav = alpha[0];
        int m_out = mrow + lid;
        int b_o = m_out / NN, nsp = m_out % NN;
        size_t obase = (size_t)b_o * CC * NN + nsp;
        #pragma unroll
        for (int cb = 0; cb < 4; cb++) {
            int c0 = half * 128 + cb * 32;
            uint32_t r[32];
            LDTM_X32(r, tmem + c0);
            asm volatile("tcgen05.wait::ld.sync.aligned;" ::: "memory");
            #pragma unroll
            for (int j = 0; j < 32; j++) spatch[lid * 33 + j] = __uint_as_float(r[j]);
            __syncwarp();
            #pragma unroll
            for (int i = 0; i < 8; i++) {
                int rr = i * 4 + (lid >> 3);
                int c4 = (lid & 7) * 4;
                int m = mrow + rr;
                int n = c0 + c4;
                float vv[4];
                #pragma unroll
                for (int e = 0; e < 4; e++) vv[e] = spatch[rr * 33 + c4 + e];
                float4 bb = *(const float4*)(bias + n);
                float4 r4 = *(const float4*)(res + (size_t)m * N + n);
                float4 g4 = *(const float4*)(gam + n);
                float4 b4 = *(const float4*)(bet + n);
                float4 u4 = *(const float4*)(rm + n);
                float4 s4 = *(const float4*)(rv + n);
                float y;
                y = r4.x + vv[0] + bb.x; vv[0] = (y - u4.x) * (g4.x * rsqrtf(s4.x + EPSL)) + b4.x + alphav * y;
                y = r4.y + vv[1] + bb.y; vv[1] = (y - u4.y) * (g4.y * rsqrtf(s4.y + EPSL)) + b4.y + alphav * y;
                y = r4.z + vv[2] + bb.z; vv[2] = (y - u4.z) * (g4.z * rsqrtf(s4.z + EPSL)) + b4.z + alphav * y;
                y = r4.w + vv[3] + bb.w; vv[3] = (y - u4.w) * (g4.w * rsqrtf(s4.w + EPSL)) + b4.w + alphav * y;
                #pragma unroll
                for (int e = 0; e < 4; e++) spatch[rr * 33 + c4 + e] = vv[e];
            }
            __syncwarp();
            #pragma unroll
            for (int cc = 0; cc < 32; cc++)
                out[obase + (size_t)(c0 + cc) * NN] = spatch[lid * 33 + cc];
            __syncwarp();
        }
    }
    __syncthreads();
    if (tid == 0)
        for (int i = 0; i < 5; i++)
            asm volatile("mbarrier.inval.shared.b64 [%0];" :: "r"(smem_u32(&s_mbar[i])) : "memory");
    __syncthreads();
    if (wid == 0)
        asm volatile("tcgen05.dealloc.cta_group::1.sync.aligned.b32 %0, %1;"
                     :: "r"(tmem), "r"(256));
#endif
}

// ---------------- flash attention on tcgen05: block = (h, b) ------------------
__global__ __launch_bounds__(256)
void k_fattn(const __grid_constant__ CUtensorMap tmQKV,
             const float* __restrict__ qkv, float* __restrict__ attnout)
{
#if TC_OK
    extern __shared__ char smem_raw[];
    __shared__ uint64_t s_mbar[3];
    __shared__ uint32_t s_tmem;

    uint32_t sb_raw = smem_u32(smem_raw);
    uint32_t tbase = (sb_raw + 1023u) & ~1023u;
    char* tptr = smem_raw + (tbase - sb_raw);

    int tid = threadIdx.x, wid = tid >> 5, lid = tid & 31;
    int h = blockIdx.x, b = blockIdx.y;
    const uint32_t QOFF = 0, KOFF = 32768, VOFF = 61440;

    if (wid == 0)
        asm volatile("tcgen05.alloc.cta_group::1.sync.aligned.shared::cta.b32 [%0], %1;"
                     :: "r"(smem_u32(&s_tmem)), "r"(512) : "memory");
    if (tid == 0)
        for (int i = 0; i < 3; i++) MBAR_INIT(smem_u32(&s_mbar[i]), 1);
    __syncthreads();
    uint32_t tmem = s_tmem;
    if (wid == 0)
        asm volatile("tcgen05.relinquish_alloc_permit.cta_group::1.sync.aligned;");

    if (tid == 0) {
        MBAR_EXPECT(smem_u32(&s_mbar[0]), 2 * 196 * 128);
        TMA_LD2D(tbase + QOFF, &tmQKV, h * 32, b * 196, smem_u32(&s_mbar[0]));
        TMA_LD2D(tbase + KOFF, &tmQKV, 256 + h * 32, b * 196, smem_u32(&s_mbar[0]));
    }

    for (int i = tid; i < 1792; i += 256)
        ((float4*)(tptr + VOFF))[i] = make_float4(0.f, 0.f, 0.f, 0.f);
    __syncthreads();
    {
        size_t vbase = (size_t)b * 196 * 768 + 512 + (size_t)h * 32;
        for (int idx = tid; idx < 196 * 32; idx += 256) {
            int m = idx >> 5, d = idx & 31;
            float v = qkv[vbase + (size_t)m * 768 + d];
            int atom = (d >> 3) + (m >> 5) * 4;
            uint32_t bo = atom * 1024 + (d & 7) * 128 + (m & 31) * 4;
            uint32_t sw = bo ^ ((bo >> 3) & 0x70);
            *(float*)(tptr + VOFF + sw) = v;
        }
    }
    __syncthreads();

    const uint32_t IDESC1 = (1u << 4) | (2u << 7) | (2u << 10) | (28u << 17) | (8u << 24);
    const uint32_t IDESC2 = (1u << 4) | (2u << 7) | (2u << 10) | (4u << 17)  | (8u << 24);

    if (tid == 0) {
        MBAR_WAIT(smem_u32(&s_mbar[0]), 0);
        asm volatile("fence.proxy.async.shared::cta;" ::: "memory");
        uint64_t qd0 = DESC_BASE | ((uint64_t)((tbase + QOFF) >> 4) & 0x3FFF);
        uint64_t qd1 = DESC_BASE | ((uint64_t)((tbase + QOFF + 16384) >> 4) & 0x3FFF);
        uint64_t kd  = DESC_BASE | ((uint64_t)((tbase + KOFF) >> 4) & 0x3FFF);
        #pragma unroll
        for (int s = 0; s < 4; s++) mma_tf32(tmem,       qd0 + s * 2, kd + s * 2, IDESC1, s > 0);
        #pragma unroll
        for (int s = 0; s < 4; s++) mma_tf32(tmem + 224, qd1 + s * 2, kd + s * 2, IDESC1, s > 0);
        asm volatile(
            "tcgen05.commit.cta_group::1.mbarrier::arrive::one.shared::cluster.b64 [%0];"
            :: "r"(smem_u32(&s_mbar[1])) : "memory");
    }
    MBAR_WAIT(smem_u32(&s_mbar[1]), 0);
    asm volatile("tcgen05.fence::after_thread_sync;" ::: "memory");

    int sub = wid & 3, tile = wid >> 2;
    uint32_t Sbase = tmem + tile * 224;
    uint32_t stoff = (uint32_t)sub << 21;
    float l = 0.f;
    const float SC = 0.17677669529663687f;
    #pragma unroll
    for (int cb = 0; cb < 7; cb++) {
        uint32_t r[32];
        LDTM_X32(r, Sbase + cb * 32);
        asm volatile("tcgen05.wait::ld.sync.aligned;" ::: "memory");
        int vlim = (cb == 6) ? 4 : 32;
        #pragma unroll
        for (int j = 0; j < 32; j++) {
            float p = 0.f;
            if (j < vlim) { p = __expf(__uint_as_float(r[j]) * SC); l += p; }
            r[j] = __float_as_uint(p);
        }
        STTM_X32(Sbase + cb * 32 + stoff, r);
        asm volatile("tcgen05.wait::st.sync.aligned;" ::: "memory");
    }
    asm volatile("tcgen05.fence::before_thread_sync;" ::: "memory");
    __syncthreads();

    if (tid == 0) {
        asm volatile("tcgen05.fence::after_thread_sync;" ::: "memory");
        uint64_t vd = DESC_BASE | ((uint64_t)((tbase + VOFF) >> 4) & 0x3FFF);
        #pragma unroll
        for (int t = 0; t < 2; t++) {
            #pragma unroll
            for (int c = 0; c < 28; c++) {
                uint64_t bd = vd + (uint64_t)((c >> 2) * 256 + (c & 3) * 2);
                mma_tf32_ts(tmem + 448 + t * 32, tmem + t * 224 + c * 8, bd, IDESC2, c > 0);
            }
        }
        asm volatile(
            "tcgen05.commit.cta_group::1.mbarrier::arrive::one.shared::cluster.b64 [%0];"
            :: "r"(smem_u32(&s_mbar[2])) : "memory");
    }
    MBAR_WAIT(smem_u32(&s_mbar[2]), 0);
    asm volatile("tcgen05.fence::after_thread_sync;" ::: "memory");

    {
        uint32_t r[32];
        LDTM_X32(r, tmem + 448 + tile * 32);
        asm volatile("tcgen05.wait::ld.sync.aligned;" ::: "memory");
        int row = tile * 128 + sub * 32 + lid;
        if (row < 196) {
            float inv = 1.f / l;
            float* op = attnout + ((size_t)(b * NN + row)) * CC + h * 32;
            #pragma unroll
            for (int i = 0; i < 8; i++) {
                float4 o = make_float4(__uint_as_float(r[i*4+0]) * inv,
                                       __uint_as_float(r[i*4+1]) * inv,
                                       __uint_as_float(r[i*4+2]) * inv,
                                       __uint_as_float(r[i*4+3]) * inv);
                *(float4*)(op + i * 4) = o;
            }
        }
    }
    __syncthreads();
    if (tid == 0)
        for (int i = 0; i < 3; i++)
            asm volatile("mbarrier.inval.shared.b64 [%0];" :: "r"(smem_u32(&s_mbar[i])) : "memory");
    __syncthreads();
    if (wid == 0)
        asm volatile("tcgen05.dealloc.cta_group::1.sync.aligned.b32 %0, %1;"
                     :: "r"(tmem), "r"(512));
#endif
}

// ---------------- host: tensormap encode --------------------------------------
typedef CUresult (*PFN_encodeTiled)(
    CUtensorMap*, CUtensorMapDataType, cuuint32_t, void*,
    const cuuint64_t*, const cuuint64_t*, const cuuint32_t*, const cuuint32_t*,
    CUtensorMapInterleave, CUtensorMapSwizzle, CUtensorMapL2promotion,
    CUtensorMapFloatOOBfill);

static void encode_2d(PFN_encodeTiled enc, CUtensorMap* tm, void* base,
                      uint64_t rows, uint64_t cols, uint32_t box_rows) {
    cuuint64_t dims[2]    = { cols, rows };
    cuuint64_t strides[1] = { cols * 4 };
    cuuint32_t box[2]     = { 32, box_rows };
    cuuint32_t estr[2]    = { 1, 1 };
    enc(tm, CU_TENSOR_MAP_DATA_TYPE_FLOAT32, 2, base, dims, strides, box, estr,
        CU_TENSOR_MAP_INTERLEAVE_NONE, CU_TENSOR_MAP_SWIZZLE_128B,
        CU_TENSOR_MAP_L2_PROMOTION_L2_128B, CU_TENSOR_MAP_FLOAT_OOB_FILL_NONE);
}

static void encode_2d_bf16(PFN_encodeTiled enc, CUtensorMap* tm, void* base,
                           uint64_t rows, uint64_t cols, uint32_t box_rows) {
    cuuint64_t dims[2]    = { cols, rows };
    cuuint64_t strides[1] = { cols * 2 };
    cuuint32_t box[2]     = { 64, box_rows };   // 64 bf16 = 128B (SW128 limit)
    cuuint32_t estr[2]    = { 1, 1 };
    enc(tm, CU_TENSOR_MAP_DATA_TYPE_BFLOAT16, 2, base, dims, strides, box, estr,
        CU_TENSOR_MAP_INTERLEAVE_NONE, CU_TENSOR_MAP_SWIZZLE_128B,
        CU_TENSOR_MAP_L2_PROMOTION_L2_128B, CU_TENSOR_MAP_FLOAT_OOB_FILL_NONE);
}

// ---------------- launch ------------------------------------------------------
extern "C" void kernel_launch(void* const* d_in, const int* in_sizes, int n_in,
                              void* d_out, int out_size) {
    const float* x      = (const float*)d_in[0];
    const float* W_qkv  = (const float*)d_in[1];
    const float* b_qkv  = (const float*)d_in[2];
    const float* W_proj = (const float*)d_in[3];
    const float* b_proj = (const float*)d_in[4];
    const float* W1     = (const float*)d_in[5];
    const float* b1     = (const float*)d_in[6];
    const float* W2     = (const float*)d_in[7];
    const float* b2     = (const float*)d_in[8];
    const float* sa_w   = (const float*)d_in[9];
    const float* sa_b   = (const float*)d_in[10];
    const float* alpha1 = (const float*)d_in[11];
    const float* gamma1 = (const float*)d_in[12];
    const float* beta1  = (const float*)d_in[13];
    const float* rm1    = (const float*)d_in[14];
    const float* rv1    = (const float*)d_in[15];
    const float* alpha2 = (const float*)d_in[16];
    const float* gamma2 = (const float*)d_in[17];
    const float* beta2  = (const float*)d_in[18];
    const float* rm2    = (const float*)d_in[19];
    const float* rv2    = (const float*)d_in[20];
    float* out = (float*)d_out;

    float *t, *qkv, *attn, *t1, *wqkvT, *wprojT, *w1T;
    __nv_bfloat16 *hbuf, *w2T;
    cudaGetSymbolAddress((void**)&t,      g_t);
    cudaGetSymbolAddress((void**)&qkv,    g_qkv);
    cudaGetSymbolAddress((void**)&attn,   g_attn);
    cudaGetSymbolAddress((void**)&t1,     g_t1);
    cudaGetSymbolAddress((void**)&hbuf,   g_h);
    cudaGetSymbolAddress((void**)&wqkvT,  g_wqkvT);
    cudaGetSymbolAddress((void**)&wprojT, g_wprojT);
    cudaGetSymbolAddress((void**)&w1T,    g_w1T);
    cudaGetSymbolAddress((void**)&w2T,    g_w2T);

    void* fn = nullptr;
    cudaDriverEntryPointQueryResult qres;
    cudaGetDriverEntryPoint("cuTensorMapEncodeTiled", &fn, cudaEnableDefault, &qres);
    PFN_encodeTiled enc = (PFN_encodeTiled)fn;

    CUtensorMap tm_t, tm_wqkv, tm_attn, tm_wproj, tm_t1, tm_w1, tm_h, tm_w2, tm_qa;
    encode_2d(enc, &tm_t,     t,      MM,   256,  128);
    encode_2d(enc, &tm_wqkv,  wqkvT,  768,  256,  128);
    encode_2d(enc, &tm_attn,  attn,   MM,   256,  128);
    encode_2d(enc, &tm_wproj, wprojT, 256,  256,  128);
    encode_2d(enc, &tm_t1,    t1,     MM,   256,  128);
    encode_2d(enc, &tm_w1,    w1T,    CMID, 256,  128);
    encode_2d_bf16(enc, &tm_h,  hbuf, MM,   CMID, 128);
    encode_2d_bf16(enc, &tm_w2, w2T,  256,  CMID, 256);
    encode_2d(enc, &tm_qa,    qkv,    MM,   768,  196);

    const int GEMM_SMEM  = 1024 + 2 * 32768;              // 66560
    const int GEMMW_SMEM = 1024 + 2 * 49152;              // 99328
    const int FATT_SMEM  = 1024 + 32768 + 28672 + 28672;  // 91136
    cudaFuncSetAttribute(k_tgemm,   cudaFuncAttributeMaxDynamicSharedMemorySize, GEMM_SMEM);
    cudaFuncSetAttribute(k_tgemm_w, cudaFuncAttributeMaxDynamicSharedMemorySize, GEMMW_SMEM);
    cudaFuncSetAttribute(k_fattn,   cudaFuncAttributeMaxDynamicSharedMemorySize, FATT_SMEM);

    dim3 tb(32, 8);
    // merged prep: 4 weight transposes (W2 -> bf16) + input transpose
    k_prep<<<15616, tb>>>(W_qkv, wqkvT, W_proj, wprojT, W1, w1T, W2, w2T, x, t);
    // QKV
    k_tgemm<<<dim3(768 / 128, MM / 128), 256, GEMM_SMEM>>>(tm_t, tm_wqkv, b_qkv, qkv,
        768, 256, 0, nullptr, nullptr, nullptr, nullptr, nullptr, nullptr, nullptr, nullptr);
    // flash attention on tensor cores
    k_fattn<<<dim3(8, BB), 256, FATT_SMEM>>>(tm_qa, qkv, attn);
    // proj + residual + repbn1
    k_tgemm<<<dim3(256 / 128, MM / 128), 256, GEMM_SMEM>>>(tm_attn, tm_wproj, b_proj, t1,
        256, 256, 1, t, gamma1, beta1, rm1, rv1, alpha1, nullptr, nullptr);
    // FFN1 + SpatialSILU -> bf16 h
    k_tgemm<<<dim3(CMID / 128, MM / 128), 256, GEMM_SMEM>>>(tm_t1, tm_w1, b1, (float*)hbuf,
        CMID, 256, 2, nullptr, nullptr, nullptr, nullptr, nullptr, nullptr, sa_w, sa_b);
    // FFN2 (bf16 wide) + residual + repbn2 -> [B,C,N]
    k_tgemm_w<<<MM / 128, 256, GEMMW_SMEM>>>(tm_h, tm_w2, b2, out,
        CMID, t1, gamma2, beta2, rm2, rv2, alpha2);
}